// round 1
// baseline (speedup 1.0000x reference)
#include <cuda_runtime.h>

#define D_MODEL 2048
#define NHEAD   16
#define HD      128
#define TSEQ    1024
#define BATCH   4

// Scratch (module-load allocated, not cudaMalloc — allowed)
__device__ float g_qkv[BATCH * TSEQ * 3 * D_MODEL];   // ~100.7 MB
__device__ float g_att[BATCH * TSEQ * D_MODEL];       // ~33.6 MB

// ---------------------------------------------------------------------------
// SGEMM: C[M,N] = A[M,K] @ B[K,N], all row-major, M%128==N%128==K%16==0
// 128x128 block tile, 16 k-slice, 256 threads, 8x8 per thread (2x2 quadrants)
// ---------------------------------------------------------------------------
#define BM  128
#define BN  128
#define BKK 16

__global__ __launch_bounds__(256, 2)
void sgemm_kernel(const float* __restrict__ A, const float* __restrict__ B,
                  float* __restrict__ C, int M, int N, int K)
{
    __shared__ float As[BKK][BM + 4];   // A stored transposed: As[k][m]
    __shared__ float Bs[BKK][BN];       // natural: Bs[k][n]

    const int tid = threadIdx.x;
    const int tx  = tid & 15;
    const int ty  = tid >> 4;

    const float* Ab = A + (size_t)blockIdx.y * BM * (size_t)K;
    const float* Bb = B + (size_t)blockIdx.x * BN;

    float acc[2][2][4][4];
#pragma unroll
    for (int ih = 0; ih < 2; ih++)
#pragma unroll
        for (int iw = 0; iw < 2; iw++)
#pragma unroll
            for (int i = 0; i < 4; i++)
#pragma unroll
                for (int j = 0; j < 4; j++)
                    acc[ih][iw][i][j] = 0.0f;

    const int arow = tid >> 2;          // 0..63 (plus +64 on 2nd iter)
    const int ak   = (tid & 3) << 2;    // 0,4,8,12
    const int brow = tid >> 5;          // 0..7 (plus +8)
    const int bcol = (tid & 31) << 2;   // 0..124

    for (int k0 = 0; k0 < K; k0 += BKK) {
#pragma unroll
        for (int i = 0; i < 2; i++) {
            const int r = arow + i * 64;
            float4 v = *(const float4*)(Ab + (size_t)r * K + k0 + ak);
            As[ak + 0][r] = v.x;
            As[ak + 1][r] = v.y;
            As[ak + 2][r] = v.z;
            As[ak + 3][r] = v.w;
        }
#pragma unroll
        for (int i = 0; i < 2; i++) {
            const int r = brow + i * 8;
            *(float4*)&Bs[r][bcol] =
                *(const float4*)(Bb + (size_t)(k0 + r) * N + bcol);
        }
        __syncthreads();

#pragma unroll
        for (int k = 0; k < BKK; k++) {
            float a[2][4], b[2][4];
            *(float4*)a[0] = *(const float4*)&As[k][ty * 4];
            *(float4*)a[1] = *(const float4*)&As[k][ty * 4 + 64];
            *(float4*)b[0] = *(const float4*)&Bs[k][tx * 4];
            *(float4*)b[1] = *(const float4*)&Bs[k][tx * 4 + 64];
#pragma unroll
            for (int ih = 0; ih < 2; ih++)
#pragma unroll
                for (int i = 0; i < 4; i++)
#pragma unroll
                    for (int iw = 0; iw < 2; iw++)
#pragma unroll
                        for (int j = 0; j < 4; j++)
                            acc[ih][iw][i][j] =
                                fmaf(a[ih][i], b[iw][j], acc[ih][iw][i][j]);
        }
        __syncthreads();
    }

#pragma unroll
    for (int ih = 0; ih < 2; ih++)
#pragma unroll
        for (int i = 0; i < 4; i++) {
            const size_t row = (size_t)blockIdx.y * BM + ih * 64 + ty * 4 + i;
            float* Cp = C + row * N + (size_t)blockIdx.x * BN + tx * 4;
#pragma unroll
            for (int iw = 0; iw < 2; iw++) {
                float4 v = make_float4(acc[ih][iw][i][0], acc[ih][iw][i][1],
                                       acc[ih][iw][i][2], acc[ih][iw][i][3]);
                *(float4*)(Cp + iw * 64) = v;
            }
        }
}

// ---------------------------------------------------------------------------
// Flash attention (fp32, causal). One block = (q-tile of 64, head, batch).
// smem: Qs[64][132], Ks[64][132], Vs[64][128], Ps[64][65]  (~114.25 KB)
// 256 threads as 16x16 (tx,ty): S rows ty+16i, cols tx+16j (i,j<4);
// O rows ty+16i, cols tx+16j (j<8). Row reductions via half-warp shuffles.
// ---------------------------------------------------------------------------
#define AQ    64
#define ASTR  132
#define PSTR  65
#define ATTN_SMEM_FLOATS (2 * 64 * ASTR + 64 * 128 + 64 * PSTR)
#define ATTN_SMEM_BYTES  (ATTN_SMEM_FLOATS * 4)

__global__ __launch_bounds__(256, 1)
void attn_kernel(const float* __restrict__ qkv, float* __restrict__ out)
{
    extern __shared__ float sm[];
    float* Qs = sm;                       // [64][132]
    float* Ks = Qs + 64 * ASTR;           // [64][132]
    float* Vs = Ks + 64 * ASTR;           // [64][128]
    float* Ps = Vs + 64 * 128;            // [64][65]  (P transposed: Ps[k][row])

    const int qt  = blockIdx.x;
    const int h   = blockIdx.y;
    const int b   = blockIdx.z;
    const int tid = threadIdx.x;
    const int tx  = tid & 15;
    const int ty  = tid >> 4;

    const size_t qrow0 = (size_t)b * TSEQ + (size_t)qt * AQ;
    const float* qbase = qkv + qrow0 * (3 * D_MODEL) + h * HD;

    // load Q tile: 64 rows x 128 cols (coalesced f4 along d)
#pragma unroll
    for (int it = 0; it < 8; it++) {
        const int idx = tid + it * 256;
        const int m   = idx >> 5;
        const int dg  = (idx & 31) << 2;
        *(float4*)&Qs[m * ASTR + dg] =
            *(const float4*)(qbase + (size_t)m * (3 * D_MODEL) + dg);
    }

    float mi[4], li[4], o[4][8];
#pragma unroll
    for (int i = 0; i < 4; i++) {
        mi[i] = -1e30f;
        li[i] = 0.0f;
#pragma unroll
        for (int j = 0; j < 8; j++) o[i][j] = 0.0f;
    }

    const float scale = 0.088388347648318447f;   // 1/sqrt(128)

    for (int kt = 0; kt <= qt; kt++) {
        __syncthreads();   // prior readers of Ks/Vs/Ps are done
        const float* kbase =
            qkv + ((size_t)b * TSEQ + (size_t)kt * AQ) * (3 * D_MODEL)
                + D_MODEL + h * HD;
        const float* vbase = kbase + D_MODEL;
#pragma unroll
        for (int it = 0; it < 8; it++) {
            const int idx = tid + it * 256;
            const int n   = idx >> 5;
            const int dg  = (idx & 31) << 2;
            *(float4*)&Ks[n * ASTR + dg] =
                *(const float4*)(kbase + (size_t)n * (3 * D_MODEL) + dg);
            *(float4*)&Vs[n * 128 + dg] =
                *(const float4*)(vbase + (size_t)n * (3 * D_MODEL) + dg);
        }
        __syncthreads();

        // ---- S = Q @ K^T (64x64, per-thread 4x4) ----
        float s[4][4];
#pragma unroll
        for (int i = 0; i < 4; i++)
#pragma unroll
            for (int j = 0; j < 4; j++) s[i][j] = 0.0f;

#pragma unroll 2
        for (int d = 0; d < HD; d += 4) {
            float a[4][4], bb[4][4];
#pragma unroll
            for (int i = 0; i < 4; i++)
                *(float4*)a[i] = *(const float4*)&Qs[(ty + 16 * i) * ASTR + d];
#pragma unroll
            for (int j = 0; j < 4; j++)
                *(float4*)bb[j] = *(const float4*)&Ks[(tx + 16 * j) * ASTR + d];
#pragma unroll
            for (int i = 0; i < 4; i++)
#pragma unroll
                for (int j = 0; j < 4; j++)
#pragma unroll
                    for (int dd = 0; dd < 4; dd++)
                        s[i][j] = fmaf(a[i][dd], bb[j][dd], s[i][j]);
        }

        // ---- scale + causal mask (only on the diagonal tile) ----
        const bool diag = (kt == qt);
#pragma unroll
        for (int i = 0; i < 4; i++)
#pragma unroll
            for (int j = 0; j < 4; j++) {
                float v = s[i][j] * scale;
                if (diag && (tx + 16 * j > ty + 16 * i)) v = -1e30f;
                s[i][j] = v;
            }

        // ---- online softmax (rows distributed across 16 lanes, half-warp) ----
#pragma unroll
        for (int i = 0; i < 4; i++) {
            float rm = fmaxf(fmaxf(s[i][0], s[i][1]), fmaxf(s[i][2], s[i][3]));
            rm = fmaxf(rm, __shfl_xor_sync(0xffffffffu, rm, 1));
            rm = fmaxf(rm, __shfl_xor_sync(0xffffffffu, rm, 2));
            rm = fmaxf(rm, __shfl_xor_sync(0xffffffffu, rm, 4));
            rm = fmaxf(rm, __shfl_xor_sync(0xffffffffu, rm, 8));
            const float mnew = fmaxf(mi[i], rm);
            const float corr = __expf(mi[i] - mnew);
            mi[i] = mnew;
            float rs = 0.0f;
#pragma unroll
            for (int j = 0; j < 4; j++) {
                const float p = __expf(s[i][j] - mnew);
                s[i][j] = p;
                rs += p;
            }
            rs += __shfl_xor_sync(0xffffffffu, rs, 1);
            rs += __shfl_xor_sync(0xffffffffu, rs, 2);
            rs += __shfl_xor_sync(0xffffffffu, rs, 4);
            rs += __shfl_xor_sync(0xffffffffu, rs, 8);
            li[i] = li[i] * corr + rs;
#pragma unroll
            for (int c = 0; c < 8; c++) o[i][c] *= corr;
        }

        // ---- stage P transposed: Ps[k][row] ----
#pragma unroll
        for (int i = 0; i < 4; i++)
#pragma unroll
            for (int j = 0; j < 4; j++)
                Ps[(tx + 16 * j) * PSTR + (ty + 16 * i)] = s[i][j];
        __syncthreads();

        // ---- O += P @ V (64x128, per-thread 4x8) ----
#pragma unroll 2
        for (int kk = 0; kk < 64; kk++) {
            float pa[4];
#pragma unroll
            for (int i = 0; i < 4; i++) pa[i] = Ps[kk * PSTR + ty + 16 * i];
            float vb[8];
#pragma unroll
            for (int j = 0; j < 8; j++) vb[j] = Vs[kk * 128 + tx + 16 * j];
#pragma unroll
            for (int i = 0; i < 4; i++)
#pragma unroll
                for (int j = 0; j < 8; j++)
                    o[i][j] = fmaf(pa[i], vb[j], o[i][j]);
        }
    }

    // ---- epilogue: normalize and write [B*T, C] ----
#pragma unroll
    for (int i = 0; i < 4; i++) {
        const float inv = 1.0f / li[i];
        const size_t row = qrow0 + ty + 16 * i;
        float* op = out + row * D_MODEL + h * HD + tx;
#pragma unroll
        for (int j = 0; j < 8; j++) op[16 * j] = o[i][j] * inv;
    }
}

// ---------------------------------------------------------------------------
extern "C" void kernel_launch(void* const* d_in, const int* in_sizes, int n_in,
                              void* d_out, int out_size)
{
    (void)in_sizes; (void)n_in; (void)out_size;
    const float* x      = (const float*)d_in[0];
    const float* w_qkv  = (const float*)d_in[1];
    const float* w_proj = (const float*)d_in[2];
    float* out = (float*)d_out;

    float* qkv = nullptr;
    float* att = nullptr;
    cudaGetSymbolAddress((void**)&qkv, g_qkv);
    cudaGetSymbolAddress((void**)&att, g_att);

    cudaFuncSetAttribute(attn_kernel,
                         cudaFuncAttributeMaxDynamicSharedMemorySize,
                         ATTN_SMEM_BYTES);

    const int M = BATCH * TSEQ;   // 4096

    // 1) qkv = x @ w_qkv   [4096,2048]x[2048,6144]
    sgemm_kernel<<<dim3(3 * D_MODEL / BN, M / BM), 256>>>(
        x, w_qkv, qkv, M, 3 * D_MODEL, D_MODEL);

    // 2) attention -> att [4096, 2048]
    attn_kernel<<<dim3(TSEQ / AQ, NHEAD, BATCH), 256, ATTN_SMEM_BYTES>>>(
        qkv, att);

    // 3) out = att @ w_proj   [4096,2048]x[2048,2048]
    sgemm_kernel<<<dim3(D_MODEL / BN, M / BM), 256>>>(
        att, w_proj, out, M, D_MODEL, D_MODEL);
}

// round 3
// speedup vs baseline: 1.7960x; 1.7960x over previous
#include <cuda_runtime.h>
#include <cuda_bf16.h>
#include <cstdint>

#define D_MODEL 2048
#define NHEAD   16
#define HD      128
#define TSEQ    1024
#define BATCH   4
#define MTOT    (BATCH * TSEQ)     // 4096
#define NQKV    (3 * D_MODEL)      // 6144

// ---------------------------------------------------------------------------
// Scratch (__device__ globals — allocation-guard safe)
// ---------------------------------------------------------------------------
__device__ float g_qkv[MTOT * NQKV];                  // 100.7 MB
__device__ float g_att[MTOT * D_MODEL];               // 33.6 MB
__device__ __nv_bfloat16 g_xhi[MTOT * D_MODEL];
__device__ __nv_bfloat16 g_xlo[MTOT * D_MODEL];
__device__ __nv_bfloat16 g_ahi[MTOT * D_MODEL];
__device__ __nv_bfloat16 g_alo[MTOT * D_MODEL];
__device__ __nv_bfloat16 g_wqhi[NQKV * D_MODEL];      // transposed [N][K]
__device__ __nv_bfloat16 g_wqlo[NQKV * D_MODEL];
__device__ __nv_bfloat16 g_wphi[D_MODEL * D_MODEL];
__device__ __nv_bfloat16 g_wplo[D_MODEL * D_MODEL];

// ---------------------------------------------------------------------------
// helpers
// ---------------------------------------------------------------------------
__device__ __forceinline__ uint32_t smem_u32(const void* p) {
    uint32_t a;
    asm("{ .reg .u64 t; cvta.to.shared.u64 t, %1; cvt.u32.u64 %0, t; }"
        : "=r"(a) : "l"(p));
    return a;
}
__device__ __forceinline__ void cpa16(uint32_t dst, const void* src) {
    asm volatile("cp.async.cg.shared.global [%0], [%1], 16;" :: "r"(dst), "l"(src));
}
__device__ __forceinline__ void cp_commit() { asm volatile("cp.async.commit_group;"); }
template <int N> __device__ __forceinline__ void cp_wait() {
    asm volatile("cp.async.wait_group %0;" :: "n"(N));
}
__device__ __forceinline__ uint32_t lds32(uint32_t a) {
    uint32_t v;
    asm("ld.shared.b32 %0, [%1];" : "=r"(v) : "r"(a));
    return v;
}
__device__ __forceinline__ void mma_bf16(float* c, const uint32_t* a,
                                         const uint32_t* b) {
    asm volatile(
        "mma.sync.aligned.m16n8k16.row.col.f32.bf16.bf16.f32 "
        "{%0,%1,%2,%3}, {%4,%5,%6,%7}, {%8,%9}, {%0,%1,%2,%3};"
        : "+f"(c[0]), "+f"(c[1]), "+f"(c[2]), "+f"(c[3])
        : "r"(a[0]), "r"(a[1]), "r"(a[2]), "r"(a[3]), "r"(b[0]), "r"(b[1]));
}

// ---------------------------------------------------------------------------
// Split fp32 -> (hi, lo) bf16 (elementwise)
// ---------------------------------------------------------------------------
__global__ __launch_bounds__(256)
void split_kernel(const float* __restrict__ in, __nv_bfloat16* __restrict__ hi,
                  __nv_bfloat16* __restrict__ lo, int n)
{
    int i = (blockIdx.x * 256 + threadIdx.x) * 4;
    if (i >= n) return;
    float4 v = *(const float4*)(in + i);
    __nv_bfloat16 h0 = __float2bfloat16(v.x);
    __nv_bfloat16 h1 = __float2bfloat16(v.y);
    __nv_bfloat16 h2 = __float2bfloat16(v.z);
    __nv_bfloat16 h3 = __float2bfloat16(v.w);
    __nv_bfloat162 hh0; hh0.x = h0; hh0.y = h1;
    __nv_bfloat162 hh1; hh1.x = h2; hh1.y = h3;
    *(__nv_bfloat162*)(hi + i)     = hh0;
    *(__nv_bfloat162*)(hi + i + 2) = hh1;
    __nv_bfloat162 ll0, ll1;
    ll0.x = __float2bfloat16(v.x - __bfloat162float(h0));
    ll0.y = __float2bfloat16(v.y - __bfloat162float(h1));
    ll1.x = __float2bfloat16(v.z - __bfloat162float(h2));
    ll1.y = __float2bfloat16(v.w - __bfloat162float(h3));
    *(__nv_bfloat162*)(lo + i)     = ll0;
    *(__nv_bfloat162*)(lo + i + 2) = ll1;
}

// ---------------------------------------------------------------------------
// Transpose + split: W fp32 [K][N] -> Whi/Wlo bf16 [N][K]
// ---------------------------------------------------------------------------
__global__ __launch_bounds__(256)
void tsplit_kernel(const float* __restrict__ W, __nv_bfloat16* __restrict__ hi,
                   __nv_bfloat16* __restrict__ lo, int K, int N)
{
    __shared__ float t[32][33];
    const int n0 = blockIdx.x * 32, k0 = blockIdx.y * 32;
    const int x = threadIdx.x & 31, y = threadIdx.x >> 5;   // y in 0..7
#pragma unroll
    for (int i = 0; i < 4; i++)
        t[y + 8 * i][x] = W[(size_t)(k0 + y + 8 * i) * N + n0 + x];
    __syncthreads();
#pragma unroll
    for (int i = 0; i < 4; i++) {
        float v = t[x][y + 8 * i];
        __nv_bfloat16 h = __float2bfloat16(v);
        size_t o = (size_t)(n0 + y + 8 * i) * K + k0 + x;
        hi[o] = h;
        lo[o] = __float2bfloat16(v - __bfloat162float(h));
    }
}

// ---------------------------------------------------------------------------
// HMMA bf16x3 GEMM: C[M,N] fp32 = A[M,K] @ B^T  (B stored [N][K] K-major)
// CTA tile 128x128, BK=32, 8 warps (2Mx4N), warp tile 64x32 (4x m16, 4x n8)
// 2-stage cp.async pipeline; padded smem rows (80B) -> conflict-free LDS frags
// ---------------------------------------------------------------------------
#define BKC        32
#define SKB        80                        // padded row stride (64B data + 16B)
#define OPB        (128 * SKB)               // 10240 per operand tile
#define STGB       (4 * OPB)                 // 40960 per stage (Ahi,Alo,Bhi,Blo)
#define GEMM_SMEM  (2 * STGB)                // 81920

__device__ __forceinline__ void load_op(uint32_t dstb,
                                        const __nv_bfloat16* __restrict__ src,
                                        int r0, int k0, int K, int tid)
{
#pragma unroll
    for (int t = 0; t < 2; t++) {
        const int i = tid + t * 256;        // 0..511
        const int row = i >> 2, seg = i & 3;
        cpa16(dstb + (uint32_t)(row * SKB + seg * 16),
              src + (size_t)(r0 + row) * K + k0 + seg * 8);
    }
}

__device__ __forceinline__ void load_stage(
    uint32_t sbase,
    const __nv_bfloat16* __restrict__ Ahi, const __nv_bfloat16* __restrict__ Alo,
    const __nv_bfloat16* __restrict__ Bhi, const __nv_bfloat16* __restrict__ Blo,
    int m0, int n0, int k0, int K, int tid)
{
    load_op(sbase + 0 * OPB, Ahi, m0, k0, K, tid);
    load_op(sbase + 1 * OPB, Alo, m0, k0, K, tid);
    load_op(sbase + 2 * OPB, Bhi, n0, k0, K, tid);
    load_op(sbase + 3 * OPB, Blo, n0, k0, K, tid);
}

__global__ __launch_bounds__(256, 2)
void gemm_hmma(const __nv_bfloat16* __restrict__ Ahi,
               const __nv_bfloat16* __restrict__ Alo,
               const __nv_bfloat16* __restrict__ Bhi,
               const __nv_bfloat16* __restrict__ Blo,
               float* __restrict__ C, int M, int N, int K)
{
    extern __shared__ char smc[];
    const uint32_t sb = smem_u32(smc);
    const int tid  = threadIdx.x;
    const int wid  = tid >> 5, lane = tid & 31;
    const int wm   = wid >> 2;          // 0..1  (64 rows each)
    const int wn   = wid & 3;           // 0..3  (32 cols each)
    const int g    = lane >> 2;         // 0..7
    const int tig  = lane & 3;          // 0..3
    const int m0 = blockIdx.y * 128, n0 = blockIdx.x * 128;

    float acc[4][4][4];
#pragma unroll
    for (int mt = 0; mt < 4; mt++)
#pragma unroll
        for (int nt = 0; nt < 4; nt++)
#pragma unroll
            for (int q = 0; q < 4; q++) acc[mt][nt][q] = 0.0f;

    const int NC = K / BKC;   // 64

    load_stage(sb, Ahi, Alo, Bhi, Blo, m0, n0, 0, K, tid);
    cp_commit();
    load_stage(sb + STGB, Ahi, Alo, Bhi, Blo, m0, n0, BKC, K, tid);
    cp_commit();

    for (int kc = 0; kc < NC; kc++) {
        if (kc == NC - 1) cp_wait<0>(); else cp_wait<1>();
        __syncthreads();

        const uint32_t st = sb + (uint32_t)(kc & 1) * STGB;
#pragma unroll
        for (int ks = 0; ks < 2; ks++) {
            const uint32_t kb = (uint32_t)(ks * 32 + tig * 4);

            uint32_t bh[4][2], bl[4][2];
            const uint32_t bbase = st + 2 * OPB + (uint32_t)((wn * 32 + g) * SKB) + kb;
#pragma unroll
            for (int nt = 0; nt < 4; nt++) {
                bh[nt][0] = lds32(bbase + nt * 8 * SKB);
                bh[nt][1] = lds32(bbase + nt * 8 * SKB + 16);
                bl[nt][0] = lds32(bbase + OPB + nt * 8 * SKB);
                bl[nt][1] = lds32(bbase + OPB + nt * 8 * SKB + 16);
            }

            const uint32_t abase = st + (uint32_t)((wm * 64 + g) * SKB) + kb;
#pragma unroll
            for (int mt = 0; mt < 4; mt++) {
                const uint32_t ab = abase + mt * 16 * SKB;
                uint32_t ah[4], al[4];
                ah[0] = lds32(ab);
                ah[1] = lds32(ab + 8 * SKB);
                ah[2] = lds32(ab + 16);
                ah[3] = lds32(ab + 8 * SKB + 16);
                al[0] = lds32(ab + OPB);
                al[1] = lds32(ab + OPB + 8 * SKB);
                al[2] = lds32(ab + OPB + 16);
                al[3] = lds32(ab + OPB + 8 * SKB + 16);
#pragma unroll
                for (int nt = 0; nt < 4; nt++) {
                    mma_bf16(acc[mt][nt], ah, bh[nt]);
                    mma_bf16(acc[mt][nt], ah, bl[nt]);
                    mma_bf16(acc[mt][nt], al, bh[nt]);
                }
            }
        }
        __syncthreads();

        if (kc + 2 < NC) {
            load_stage(st, Ahi, Alo, Bhi, Blo, m0, n0, (kc + 2) * BKC, K, tid);
            cp_commit();
        }
    }

    // epilogue: each lane owns rows (g, g+8) of each m16 tile, col pair 2*tig
#pragma unroll
    for (int mt = 0; mt < 4; mt++) {
        const int row = m0 + wm * 64 + mt * 16 + g;
#pragma unroll
        for (int nt = 0; nt < 4; nt++) {
            const int col = n0 + wn * 32 + nt * 8 + tig * 2;
            float2 v0 = make_float2(acc[mt][nt][0], acc[mt][nt][1]);
            float2 v1 = make_float2(acc[mt][nt][2], acc[mt][nt][3]);
            *(float2*)&C[(size_t)row * N + col]       = v0;
            *(float2*)&C[(size_t)(row + 8) * N + col] = v1;
        }
    }
}

// ---------------------------------------------------------------------------
// Flash attention (fp32, causal) — unchanged (known correct)
// ---------------------------------------------------------------------------
#define AQ    64
#define ASTR  132
#define PSTR  65
#define ATTN_SMEM_FLOATS (2 * 64 * ASTR + 64 * 128 + 64 * PSTR)
#define ATTN_SMEM_BYTES  (ATTN_SMEM_FLOATS * 4)

__global__ __launch_bounds__(256, 1)
void attn_kernel(const float* __restrict__ qkv, float* __restrict__ out)
{
    extern __shared__ float sm[];
    float* Qs = sm;
    float* Ks = Qs + 64 * ASTR;
    float* Vs = Ks + 64 * ASTR;
    float* Ps = Vs + 64 * 128;

    const int qt  = blockIdx.x;
    const int h   = blockIdx.y;
    const int b   = blockIdx.z;
    const int tid = threadIdx.x;
    const int tx  = tid & 15;
    const int ty  = tid >> 4;

    const size_t qrow0 = (size_t)b * TSEQ + (size_t)qt * AQ;
    const float* qbase = qkv + qrow0 * (3 * D_MODEL) + h * HD;

#pragma unroll
    for (int it = 0; it < 8; it++) {
        const int idx = tid + it * 256;
        const int m   = idx >> 5;
        const int dg  = (idx & 31) << 2;
        *(float4*)&Qs[m * ASTR + dg] =
            *(const float4*)(qbase + (size_t)m * (3 * D_MODEL) + dg);
    }

    float mi[4], li[4], o[4][8];
#pragma unroll
    for (int i = 0; i < 4; i++) {
        mi[i] = -1e30f;
        li[i] = 0.0f;
#pragma unroll
        for (int j = 0; j < 8; j++) o[i][j] = 0.0f;
    }

    const float scale = 0.088388347648318447f;

    for (int kt = 0; kt <= qt; kt++) {
        __syncthreads();
        const float* kbase =
            qkv + ((size_t)b * TSEQ + (size_t)kt * AQ) * (3 * D_MODEL)
                + D_MODEL + h * HD;
        const float* vbase = kbase + D_MODEL;
#pragma unroll
        for (int it = 0; it < 8; it++) {
            const int idx = tid + it * 256;
            const int n   = idx >> 5;
            const int dg  = (idx & 31) << 2;
            *(float4*)&Ks[n * ASTR + dg] =
                *(const float4*)(kbase + (size_t)n * (3 * D_MODEL) + dg);
            *(float4*)&Vs[n * 128 + dg] =
                *(const float4*)(vbase + (size_t)n * (3 * D_MODEL) + dg);
        }
        __syncthreads();

        float s[4][4];
#pragma unroll
        for (int i = 0; i < 4; i++)
#pragma unroll
            for (int j = 0; j < 4; j++) s[i][j] = 0.0f;

#pragma unroll 2
        for (int d = 0; d < HD; d += 4) {
            float a[4][4], bb[4][4];
#pragma unroll
            for (int i = 0; i < 4; i++)
                *(float4*)a[i] = *(const float4*)&Qs[(ty + 16 * i) * ASTR + d];
#pragma unroll
            for (int j = 0; j < 4; j++)
                *(float4*)bb[j] = *(const float4*)&Ks[(tx + 16 * j) * ASTR + d];
#pragma unroll
            for (int i = 0; i < 4; i++)
#pragma unroll
                for (int j = 0; j < 4; j++)
#pragma unroll
                    for (int dd = 0; dd < 4; dd++)
                        s[i][j] = fmaf(a[i][dd], bb[j][dd], s[i][j]);
        }

        const bool diag = (kt == qt);
#pragma unroll
        for (int i = 0; i < 4; i++)
#pragma unroll
            for (int j = 0; j < 4; j++) {
                float v = s[i][j] * scale;
                if (diag && (tx + 16 * j > ty + 16 * i)) v = -1e30f;
                s[i][j] = v;
            }

#pragma unroll
        for (int i = 0; i < 4; i++) {
            float rm = fmaxf(fmaxf(s[i][0], s[i][1]), fmaxf(s[i][2], s[i][3]));
            rm = fmaxf(rm, __shfl_xor_sync(0xffffffffu, rm, 1));
            rm = fmaxf(rm, __shfl_xor_sync(0xffffffffu, rm, 2));
            rm = fmaxf(rm, __shfl_xor_sync(0xffffffffu, rm, 4));
            rm = fmaxf(rm, __shfl_xor_sync(0xffffffffu, rm, 8));
            const float mnew = fmaxf(mi[i], rm);
            const float corr = __expf(mi[i] - mnew);
            mi[i] = mnew;
            float rs = 0.0f;
#pragma unroll
            for (int j = 0; j < 4; j++) {
                const float p = __expf(s[i][j] - mnew);
                s[i][j] = p;
                rs += p;
            }
            rs += __shfl_xor_sync(0xffffffffu, rs, 1);
            rs += __shfl_xor_sync(0xffffffffu, rs, 2);
            rs += __shfl_xor_sync(0xffffffffu, rs, 4);
            rs += __shfl_xor_sync(0xffffffffu, rs, 8);
            li[i] = li[i] * corr + rs;
#pragma unroll
            for (int c = 0; c < 8; c++) o[i][c] *= corr;
        }

#pragma unroll
        for (int i = 0; i < 4; i++)
#pragma unroll
            for (int j = 0; j < 4; j++)
                Ps[(tx + 16 * j) * PSTR + (ty + 16 * i)] = s[i][j];
        __syncthreads();

#pragma unroll 2
        for (int kk = 0; kk < 64; kk++) {
            float pa[4];
#pragma unroll
            for (int i = 0; i < 4; i++) pa[i] = Ps[kk * PSTR + ty + 16 * i];
            float vb[8];
#pragma unroll
            for (int j = 0; j < 8; j++) vb[j] = Vs[kk * 128 + tx + 16 * j];
#pragma unroll
            for (int i = 0; i < 4; i++)
#pragma unroll
                for (int j = 0; j < 8; j++)
                    o[i][j] = fmaf(pa[i], vb[j], o[i][j]);
        }
    }

#pragma unroll
    for (int i = 0; i < 4; i++) {
        const float inv = 1.0f / li[i];
        const size_t row = qrow0 + ty + 16 * i;
        float* op = out + row * D_MODEL + h * HD + tx;
#pragma unroll
        for (int j = 0; j < 8; j++) op[16 * j] = o[i][j] * inv;
    }
}

// ---------------------------------------------------------------------------
extern "C" void kernel_launch(void* const* d_in, const int* in_sizes, int n_in,
                              void* d_out, int out_size)
{
    (void)in_sizes; (void)n_in; (void)out_size;
    const float* x      = (const float*)d_in[0];
    const float* w_qkv  = (const float*)d_in[1];
    const float* w_proj = (const float*)d_in[2];
    float* out = (float*)d_out;

    float *qkv, *att;
    __nv_bfloat16 *xhi, *xlo, *ahi, *alo, *wqhi, *wqlo, *wphi, *wplo;
    cudaGetSymbolAddress((void**)&qkv,  g_qkv);
    cudaGetSymbolAddress((void**)&att,  g_att);
    cudaGetSymbolAddress((void**)&xhi,  g_xhi);
    cudaGetSymbolAddress((void**)&xlo,  g_xlo);
    cudaGetSymbolAddress((void**)&ahi,  g_ahi);
    cudaGetSymbolAddress((void**)&alo,  g_alo);
    cudaGetSymbolAddress((void**)&wqhi, g_wqhi);
    cudaGetSymbolAddress((void**)&wqlo, g_wqlo);
    cudaGetSymbolAddress((void**)&wphi, g_wphi);
    cudaGetSymbolAddress((void**)&wplo, g_wplo);

    cudaFuncSetAttribute(gemm_hmma,
                         cudaFuncAttributeMaxDynamicSharedMemorySize, GEMM_SMEM);
    cudaFuncSetAttribute(attn_kernel,
                         cudaFuncAttributeMaxDynamicSharedMemorySize, ATTN_SMEM_BYTES);

    const int nx = MTOT * D_MODEL;   // 8.39M

    // 1) split x -> bf16 hi/lo
    split_kernel<<<nx / 4 / 256, 256>>>(x, xhi, xlo, nx);
    // 2) transpose+split weights -> [N][K] bf16 hi/lo
    tsplit_kernel<<<dim3(NQKV / 32, D_MODEL / 32), 256>>>(w_qkv, wqhi, wqlo,
                                                          D_MODEL, NQKV);
    tsplit_kernel<<<dim3(D_MODEL / 32, D_MODEL / 32), 256>>>(w_proj, wphi, wplo,
                                                             D_MODEL, D_MODEL);
    // 3) qkv = x @ w_qkv   (HMMA bf16x3)
    gemm_hmma<<<dim3(NQKV / 128, MTOT / 128), 256, GEMM_SMEM>>>(
        xhi, xlo, wqhi, wqlo, qkv, MTOT, NQKV, D_MODEL);
    // 4) attention
    attn_kernel<<<dim3(TSEQ / AQ, NHEAD, BATCH), 256, ATTN_SMEM_BYTES>>>(qkv, att);
    // 5) split attention output
    split_kernel<<<nx / 4 / 256, 256>>>(att, ahi, alo, nx);
    // 6) out = att @ w_proj (HMMA bf16x3)
    gemm_hmma<<<dim3(D_MODEL / 128, MTOT / 128), 256, GEMM_SMEM>>>(
        ahi, alo, wphi, wplo, out, MTOT, D_MODEL, D_MODEL);
}

// round 4
// speedup vs baseline: 1.9511x; 1.0863x over previous
#include <cuda_runtime.h>
#include <cuda_bf16.h>
#include <cstdint>

#define D_MODEL 2048
#define NHEAD   16
#define HD      128
#define TSEQ    1024
#define BATCH   4
#define MTOT    (BATCH * TSEQ)     // 4096
#define NQKV    (3 * D_MODEL)      // 6144

// ---------------------------------------------------------------------------
// Scratch (__device__ globals — allocation-guard safe)
// ---------------------------------------------------------------------------
__device__ float g_qkv[MTOT * NQKV];                  // fp32 qkv for attention
__device__ __nv_bfloat16 g_xhi[MTOT * D_MODEL];
__device__ __nv_bfloat16 g_xlo[MTOT * D_MODEL];
__device__ __nv_bfloat16 g_ahi[MTOT * D_MODEL];       // attention out, split
__device__ __nv_bfloat16 g_alo[MTOT * D_MODEL];
__device__ __nv_bfloat16 g_wqhi[NQKV * D_MODEL];      // transposed [N][K]
__device__ __nv_bfloat16 g_wqlo[NQKV * D_MODEL];
__device__ __nv_bfloat16 g_wphi[D_MODEL * D_MODEL];
__device__ __nv_bfloat16 g_wplo[D_MODEL * D_MODEL];

// ---------------------------------------------------------------------------
// helpers
// ---------------------------------------------------------------------------
__device__ __forceinline__ uint32_t smem_u32(const void* p) {
    uint32_t a;
    asm("{ .reg .u64 t; cvta.to.shared.u64 t, %1; cvt.u32.u64 %0, t; }"
        : "=r"(a) : "l"(p));
    return a;
}
__device__ __forceinline__ void cpa16(uint32_t dst, const void* src) {
    asm volatile("cp.async.cg.shared.global [%0], [%1], 16;" :: "r"(dst), "l"(src));
}
__device__ __forceinline__ void cp_commit() { asm volatile("cp.async.commit_group;"); }
template <int N> __device__ __forceinline__ void cp_wait() {
    asm volatile("cp.async.wait_group %0;" :: "n"(N));
}
__device__ __forceinline__ void ldsm4(uint32_t* r, uint32_t a) {
    asm volatile("ldmatrix.sync.aligned.m8n8.x4.shared.b16 {%0,%1,%2,%3}, [%4];"
        : "=r"(r[0]), "=r"(r[1]), "=r"(r[2]), "=r"(r[3]) : "r"(a));
}
__device__ __forceinline__ void mma_bf16(float* c, const uint32_t* a,
                                         const uint32_t* b) {
    asm volatile(
        "mma.sync.aligned.m16n8k16.row.col.f32.bf16.bf16.f32 "
        "{%0,%1,%2,%3}, {%4,%5,%6,%7}, {%8,%9}, {%0,%1,%2,%3};"
        : "+f"(c[0]), "+f"(c[1]), "+f"(c[2]), "+f"(c[3])
        : "r"(a[0]), "r"(a[1]), "r"(a[2]), "r"(a[3]), "r"(b[0]), "r"(b[1]));
}

// ---------------------------------------------------------------------------
// Split fp32 -> (hi, lo) bf16 (elementwise)
// ---------------------------------------------------------------------------
__global__ __launch_bounds__(256)
void split_kernel(const float* __restrict__ in, __nv_bfloat16* __restrict__ hi,
                  __nv_bfloat16* __restrict__ lo, int n)
{
    int i = (blockIdx.x * 256 + threadIdx.x) * 4;
    if (i >= n) return;
    float4 v = *(const float4*)(in + i);
    __nv_bfloat16 h0 = __float2bfloat16(v.x);
    __nv_bfloat16 h1 = __float2bfloat16(v.y);
    __nv_bfloat16 h2 = __float2bfloat16(v.z);
    __nv_bfloat16 h3 = __float2bfloat16(v.w);
    __nv_bfloat162 hh0; hh0.x = h0; hh0.y = h1;
    __nv_bfloat162 hh1; hh1.x = h2; hh1.y = h3;
    *(__nv_bfloat162*)(hi + i)     = hh0;
    *(__nv_bfloat162*)(hi + i + 2) = hh1;
    __nv_bfloat162 ll0, ll1;
    ll0.x = __float2bfloat16(v.x - __bfloat162float(h0));
    ll0.y = __float2bfloat16(v.y - __bfloat162float(h1));
    ll1.x = __float2bfloat16(v.z - __bfloat162float(h2));
    ll1.y = __float2bfloat16(v.w - __bfloat162float(h3));
    *(__nv_bfloat162*)(lo + i)     = ll0;
    *(__nv_bfloat162*)(lo + i + 2) = ll1;
}

// ---------------------------------------------------------------------------
// Transpose + split: W fp32 [K][N] -> Whi/Wlo bf16 [N][K]
// ---------------------------------------------------------------------------
__global__ __launch_bounds__(256)
void tsplit_kernel(const float* __restrict__ W, __nv_bfloat16* __restrict__ hi,
                   __nv_bfloat16* __restrict__ lo, int K, int N)
{
    __shared__ float t[32][33];
    const int n0 = blockIdx.x * 32, k0 = blockIdx.y * 32;
    const int x = threadIdx.x & 31, y = threadIdx.x >> 5;   // y in 0..7
#pragma unroll
    for (int i = 0; i < 4; i++)
        t[y + 8 * i][x] = W[(size_t)(k0 + y + 8 * i) * N + n0 + x];
    __syncthreads();
#pragma unroll
    for (int i = 0; i < 4; i++) {
        float v = t[x][y + 8 * i];
        __nv_bfloat16 h = __float2bfloat16(v);
        size_t o = (size_t)(n0 + y + 8 * i) * K + k0 + x;
        hi[o] = h;
        lo[o] = __float2bfloat16(v - __bfloat162float(h));
    }
}

// ---------------------------------------------------------------------------
// HMMA bf16x3 GEMM: C[M,N] fp32 = A[M,K] @ B^T  (B stored [N][K] K-major)
// CTA tile 128x128, BK=32, 8 warps (2Mx4N), warp tile 64x32 (4x m16, 4x n8)
// 2-stage cp.async pipeline; 80B-padded rows; ldmatrix.x4 fragment loads
// ---------------------------------------------------------------------------
#define BKC        32
#define SKB        80                        // padded row stride (64B data + 16B)
#define OPB        (128 * SKB)               // 10240 per operand tile
#define STGB       (4 * OPB)                 // 40960 per stage (Ahi,Alo,Bhi,Blo)
#define GEMM_SMEM  (2 * STGB)                // 81920

__device__ __forceinline__ void load_op(uint32_t dstb,
                                        const __nv_bfloat16* __restrict__ src,
                                        int r0, int k0, int K, int tid)
{
#pragma unroll
    for (int t = 0; t < 2; t++) {
        const int i = tid + t * 256;        // 0..511
        const int row = i >> 2, seg = i & 3;
        cpa16(dstb + (uint32_t)(row * SKB + seg * 16),
              src + (size_t)(r0 + row) * K + k0 + seg * 8);
    }
}

__device__ __forceinline__ void load_stage(
    uint32_t sbase,
    const __nv_bfloat16* __restrict__ Ahi, const __nv_bfloat16* __restrict__ Alo,
    const __nv_bfloat16* __restrict__ Bhi, const __nv_bfloat16* __restrict__ Blo,
    int m0, int n0, int k0, int K, int tid)
{
    load_op(sbase + 0 * OPB, Ahi, m0, k0, K, tid);
    load_op(sbase + 1 * OPB, Alo, m0, k0, K, tid);
    load_op(sbase + 2 * OPB, Bhi, n0, k0, K, tid);
    load_op(sbase + 3 * OPB, Blo, n0, k0, K, tid);
}

__global__ __launch_bounds__(256, 2)
void gemm_hmma(const __nv_bfloat16* __restrict__ Ahi,
               const __nv_bfloat16* __restrict__ Alo,
               const __nv_bfloat16* __restrict__ Bhi,
               const __nv_bfloat16* __restrict__ Blo,
               float* __restrict__ C, int M, int N, int K)
{
    extern __shared__ char smc[];
    const uint32_t sb = smem_u32(smc);
    const int tid  = threadIdx.x;
    const int wid  = tid >> 5, lane = tid & 31;
    const int wm   = wid >> 2;          // 0..1  (64 rows each)
    const int wn   = wid & 3;           // 0..3  (32 cols each)
    const int g    = lane >> 2;         // 0..7
    const int tig  = lane & 3;          // 0..3
    const int m0 = blockIdx.y * 128, n0 = blockIdx.x * 128;

    // ldmatrix per-lane source rows/halves
    const int lrow  = lane & 15;            // A: row within m16
    const int lhalf = lane >> 4;            // A: k-half (0/1)
    const int brow  = (lane & 7) | ((lane & 16) >> 1);  // B: row within nt-pair
    const int bhalf = (lane >> 3) & 1;      // B: k-half

    float acc[4][4][4];
#pragma unroll
    for (int mt = 0; mt < 4; mt++)
#pragma unroll
        for (int nt = 0; nt < 4; nt++)
#pragma unroll
            for (int q = 0; q < 4; q++) acc[mt][nt][q] = 0.0f;

    const int NC = K / BKC;   // K/32

    load_stage(sb, Ahi, Alo, Bhi, Blo, m0, n0, 0, K, tid);
    cp_commit();
    load_stage(sb + STGB, Ahi, Alo, Bhi, Blo, m0, n0, BKC, K, tid);
    cp_commit();

    for (int kc = 0; kc < NC; kc++) {
        if (kc == NC - 1) cp_wait<0>(); else cp_wait<1>();
        __syncthreads();

        const uint32_t st = sb + (uint32_t)(kc & 1) * STGB;
        const uint32_t aB = st + (uint32_t)((wm * 64 + lrow) * SKB + lhalf * 16);
        const uint32_t bB = st + 2u * OPB
                          + (uint32_t)((wn * 32 + brow) * SKB + bhalf * 16);
#pragma unroll
        for (int ks = 0; ks < 2; ks++) {
            const uint32_t kb = (uint32_t)(ks * 32);

            uint32_t bh[2][4], bl[2][4];
#pragma unroll
            for (int pr = 0; pr < 2; pr++) {
                ldsm4(bh[pr], bB + (uint32_t)(pr * 16 * SKB) + kb);
                ldsm4(bl[pr], bB + OPB + (uint32_t)(pr * 16 * SKB) + kb);
            }
#pragma unroll
            for (int mt = 0; mt < 4; mt++) {
                uint32_t ah[4], al[4];
                ldsm4(ah, aB + (uint32_t)(mt * 16 * SKB) + kb);
                ldsm4(al, aB + OPB + (uint32_t)(mt * 16 * SKB) + kb);
#pragma unroll
                for (int nt = 0; nt < 4; nt++) {
                    const uint32_t* bhp = &bh[nt >> 1][(nt & 1) * 2];
                    const uint32_t* blp = &bl[nt >> 1][(nt & 1) * 2];
                    mma_bf16(acc[mt][nt], ah, bhp);
                    mma_bf16(acc[mt][nt], ah, blp);
                    mma_bf16(acc[mt][nt], al, bhp);
                }
            }
        }
        __syncthreads();

        if (kc + 2 < NC) {
            load_stage(st, Ahi, Alo, Bhi, Blo, m0, n0, (kc + 2) * BKC, K, tid);
            cp_commit();
        }
    }

    // epilogue: each lane owns rows (g, g+8) of each m16 tile, col pair 2*tig
#pragma unroll
    for (int mt = 0; mt < 4; mt++) {
        const int row = m0 + wm * 64 + mt * 16 + g;
#pragma unroll
        for (int nt = 0; nt < 4; nt++) {
            const int col = n0 + wn * 32 + nt * 8 + tig * 2;
            float2 v0 = make_float2(acc[mt][nt][0], acc[mt][nt][1]);
            float2 v1 = make_float2(acc[mt][nt][2], acc[mt][nt][3]);
            *(float2*)&C[(size_t)row * N + col]       = v0;
            *(float2*)&C[(size_t)(row + 8) * N + col] = v1;
        }
    }
}

// ---------------------------------------------------------------------------
// Flash attention (fp32, causal). Epilogue writes split bf16 (hi/lo) for the
// projection GEMM.
// ---------------------------------------------------------------------------
#define AQ    64
#define ASTR  132
#define PSTR  65
#define ATTN_SMEM_FLOATS (2 * 64 * ASTR + 64 * 128 + 64 * PSTR)
#define ATTN_SMEM_BYTES  (ATTN_SMEM_FLOATS * 4)

__global__ __launch_bounds__(256, 1)
void attn_kernel(const float* __restrict__ qkv,
                 __nv_bfloat16* __restrict__ ohi,
                 __nv_bfloat16* __restrict__ olo)
{
    extern __shared__ float sm[];
    float* Qs = sm;
    float* Ks = Qs + 64 * ASTR;
    float* Vs = Ks + 64 * ASTR;
    float* Ps = Vs + 64 * 128;

    const int qt  = blockIdx.x;
    const int h   = blockIdx.y;
    const int b   = blockIdx.z;
    const int tid = threadIdx.x;
    const int tx  = tid & 15;
    const int ty  = tid >> 4;

    const size_t qrow0 = (size_t)b * TSEQ + (size_t)qt * AQ;
    const float* qbase = qkv + qrow0 * (3 * D_MODEL) + h * HD;

#pragma unroll
    for (int it = 0; it < 8; it++) {
        const int idx = tid + it * 256;
        const int m   = idx >> 5;
        const int dg  = (idx & 31) << 2;
        *(float4*)&Qs[m * ASTR + dg] =
            *(const float4*)(qbase + (size_t)m * (3 * D_MODEL) + dg);
    }

    float mi[4], li[4], o[4][8];
#pragma unroll
    for (int i = 0; i < 4; i++) {
        mi[i] = -1e30f;
        li[i] = 0.0f;
#pragma unroll
        for (int j = 0; j < 8; j++) o[i][j] = 0.0f;
    }

    const float scale = 0.088388347648318447f;

    for (int kt = 0; kt <= qt; kt++) {
        __syncthreads();
        const float* kbase =
            qkv + ((size_t)b * TSEQ + (size_t)kt * AQ) * (3 * D_MODEL)
                + D_MODEL + h * HD;
        const float* vbase = kbase + D_MODEL;
#pragma unroll
        for (int it = 0; it < 8; it++) {
            const int idx = tid + it * 256;
            const int n   = idx >> 5;
            const int dg  = (idx & 31) << 2;
            *(float4*)&Ks[n * ASTR + dg] =
                *(const float4*)(kbase + (size_t)n * (3 * D_MODEL) + dg);
            *(float4*)&Vs[n * 128 + dg] =
                *(const float4*)(vbase + (size_t)n * (3 * D_MODEL) + dg);
        }
        __syncthreads();

        float s[4][4];
#pragma unroll
        for (int i = 0; i < 4; i++)
#pragma unroll
            for (int j = 0; j < 4; j++) s[i][j] = 0.0f;

#pragma unroll 2
        for (int d = 0; d < HD; d += 4) {
            float a[4][4], bb[4][4];
#pragma unroll
            for (int i = 0; i < 4; i++)
                *(float4*)a[i] = *(const float4*)&Qs[(ty + 16 * i) * ASTR + d];
#pragma unroll
            for (int j = 0; j < 4; j++)
                *(float4*)bb[j] = *(const float4*)&Ks[(tx + 16 * j) * ASTR + d];
#pragma unroll
            for (int i = 0; i < 4; i++)
#pragma unroll
                for (int j = 0; j < 4; j++)
#pragma unroll
                    for (int dd = 0; dd < 4; dd++)
                        s[i][j] = fmaf(a[i][dd], bb[j][dd], s[i][j]);
        }

        const bool diag = (kt == qt);
#pragma unroll
        for (int i = 0; i < 4; i++)
#pragma unroll
            for (int j = 0; j < 4; j++) {
                float v = s[i][j] * scale;
                if (diag && (tx + 16 * j > ty + 16 * i)) v = -1e30f;
                s[i][j] = v;
            }

#pragma unroll
        for (int i = 0; i < 4; i++) {
            float rm = fmaxf(fmaxf(s[i][0], s[i][1]), fmaxf(s[i][2], s[i][3]));
            rm = fmaxf(rm, __shfl_xor_sync(0xffffffffu, rm, 1));
            rm = fmaxf(rm, __shfl_xor_sync(0xffffffffu, rm, 2));
            rm = fmaxf(rm, __shfl_xor_sync(0xffffffffu, rm, 4));
            rm = fmaxf(rm, __shfl_xor_sync(0xffffffffu, rm, 8));
            const float mnew = fmaxf(mi[i], rm);
            const float corr = __expf(mi[i] - mnew);
            mi[i] = mnew;
            float rs = 0.0f;
#pragma unroll
            for (int j = 0; j < 4; j++) {
                const float p = __expf(s[i][j] - mnew);
                s[i][j] = p;
                rs += p;
            }
            rs += __shfl_xor_sync(0xffffffffu, rs, 1);
            rs += __shfl_xor_sync(0xffffffffu, rs, 2);
            rs += __shfl_xor_sync(0xffffffffu, rs, 4);
            rs += __shfl_xor_sync(0xffffffffu, rs, 8);
            li[i] = li[i] * corr + rs;
#pragma unroll
            for (int c = 0; c < 8; c++) o[i][c] *= corr;
        }

#pragma unroll
        for (int i = 0; i < 4; i++)
#pragma unroll
            for (int j = 0; j < 4; j++)
                Ps[(tx + 16 * j) * PSTR + (ty + 16 * i)] = s[i][j];
        __syncthreads();

#pragma unroll 2
        for (int kk = 0; kk < 64; kk++) {
            float pa[4];
#pragma unroll
            for (int i = 0; i < 4; i++) pa[i] = Ps[kk * PSTR + ty + 16 * i];
            float vb[8];
#pragma unroll
            for (int j = 0; j < 8; j++) vb[j] = Vs[kk * 128 + tx + 16 * j];
#pragma unroll
            for (int i = 0; i < 4; i++)
#pragma unroll
                for (int j = 0; j < 8; j++)
                    o[i][j] = fmaf(pa[i], vb[j], o[i][j]);
        }
    }

    // epilogue: normalize, split to bf16 hi/lo, write [B*T, C]
#pragma unroll
    for (int i = 0; i < 4; i++) {
        const float inv = 1.0f / li[i];
        const size_t row = qrow0 + ty + 16 * i;
        __nv_bfloat16* hp = ohi + row * D_MODEL + h * HD + tx;
        __nv_bfloat16* lp = olo + row * D_MODEL + h * HD + tx;
#pragma unroll
        for (int j = 0; j < 8; j++) {
            const float v = o[i][j] * inv;
            const __nv_bfloat16 hv = __float2bfloat16(v);
            hp[16 * j] = hv;
            lp[16 * j] = __float2bfloat16(v - __bfloat162float(hv));
        }
    }
}

// ---------------------------------------------------------------------------
extern "C" void kernel_launch(void* const* d_in, const int* in_sizes, int n_in,
                              void* d_out, int out_size)
{
    (void)in_sizes; (void)n_in; (void)out_size;
    const float* x      = (const float*)d_in[0];
    const float* w_qkv  = (const float*)d_in[1];
    const float* w_proj = (const float*)d_in[2];
    float* out = (float*)d_out;

    float *qkv;
    __nv_bfloat16 *xhi, *xlo, *ahi, *alo, *wqhi, *wqlo, *wphi, *wplo;
    cudaGetSymbolAddress((void**)&qkv,  g_qkv);
    cudaGetSymbolAddress((void**)&xhi,  g_xhi);
    cudaGetSymbolAddress((void**)&xlo,  g_xlo);
    cudaGetSymbolAddress((void**)&ahi,  g_ahi);
    cudaGetSymbolAddress((void**)&alo,  g_alo);
    cudaGetSymbolAddress((void**)&wqhi, g_wqhi);
    cudaGetSymbolAddress((void**)&wqlo, g_wqlo);
    cudaGetSymbolAddress((void**)&wphi, g_wphi);
    cudaGetSymbolAddress((void**)&wplo, g_wplo);

    cudaFuncSetAttribute(gemm_hmma,
                         cudaFuncAttributeMaxDynamicSharedMemorySize, GEMM_SMEM);
    cudaFuncSetAttribute(attn_kernel,
                         cudaFuncAttributeMaxDynamicSharedMemorySize, ATTN_SMEM_BYTES);

    const int nx = MTOT * D_MODEL;   // 8.39M

    // 1) split x -> bf16 hi/lo
    split_kernel<<<nx / 4 / 256, 256>>>(x, xhi, xlo, nx);
    // 2) transpose+split weights -> [N][K] bf16 hi/lo
    tsplit_kernel<<<dim3(NQKV / 32, D_MODEL / 32), 256>>>(w_qkv, wqhi, wqlo,
                                                          D_MODEL, NQKV);
    tsplit_kernel<<<dim3(D_MODEL / 32, D_MODEL / 32), 256>>>(w_proj, wphi, wplo,
                                                             D_MODEL, D_MODEL);
    // 3) qkv = x @ w_qkv   (HMMA bf16x3, ldmatrix)
    gemm_hmma<<<dim3(NQKV / 128, MTOT / 128), 256, GEMM_SMEM>>>(
        xhi, xlo, wqhi, wqlo, qkv, MTOT, NQKV, D_MODEL);
    // 4) attention (writes split bf16 directly)
    attn_kernel<<<dim3(TSEQ / AQ, NHEAD, BATCH), 256, ATTN_SMEM_BYTES>>>(
        qkv, ahi, alo);
    // 5) out = att @ w_proj (HMMA bf16x3, ldmatrix)
    gemm_hmma<<<dim3(D_MODEL / 128, MTOT / 128), 256, GEMM_SMEM>>>(
        ahi, alo, wphi, wplo, out, MTOT, D_MODEL, D_MODEL);
}

// round 5
// speedup vs baseline: 2.6449x; 1.3556x over previous
#include <cuda_runtime.h>
#include <cuda_bf16.h>
#include <cstdint>

#define D_MODEL 2048
#define NHEAD   16
#define HD      128
#define TSEQ    1024
#define BATCH   4
#define MTOT    (BATCH * TSEQ)     // 4096
#define NQKV    (3 * D_MODEL)      // 6144

// ---------------------------------------------------------------------------
// Scratch (__device__ globals — allocation-guard safe)
// ---------------------------------------------------------------------------
__device__ __nv_bfloat16 g_qkvhi[MTOT * NQKV];        // split qkv (50.3 MB)
__device__ __nv_bfloat16 g_qkvlo[MTOT * NQKV];
__device__ __nv_bfloat16 g_xhi[MTOT * D_MODEL];
__device__ __nv_bfloat16 g_xlo[MTOT * D_MODEL];
__device__ __nv_bfloat16 g_ahi[MTOT * D_MODEL];       // attention out, split
__device__ __nv_bfloat16 g_alo[MTOT * D_MODEL];
__device__ __nv_bfloat16 g_wqhi[NQKV * D_MODEL];      // transposed [N][K]
__device__ __nv_bfloat16 g_wqlo[NQKV * D_MODEL];
__device__ __nv_bfloat16 g_wphi[D_MODEL * D_MODEL];
__device__ __nv_bfloat16 g_wplo[D_MODEL * D_MODEL];

// ---------------------------------------------------------------------------
// helpers
// ---------------------------------------------------------------------------
__device__ __forceinline__ uint32_t smem_u32(const void* p) {
    uint32_t a;
    asm("{ .reg .u64 t; cvta.to.shared.u64 t, %1; cvt.u32.u64 %0, t; }"
        : "=r"(a) : "l"(p));
    return a;
}
__device__ __forceinline__ void cpa16(uint32_t dst, const void* src) {
    asm volatile("cp.async.cg.shared.global [%0], [%1], 16;" :: "r"(dst), "l"(src));
}
__device__ __forceinline__ void cp_commit() { asm volatile("cp.async.commit_group;"); }
template <int N> __device__ __forceinline__ void cp_wait() {
    asm volatile("cp.async.wait_group %0;" :: "n"(N));
}
__device__ __forceinline__ void ldsm4(uint32_t* r, uint32_t a) {
    asm volatile("ldmatrix.sync.aligned.m8n8.x4.shared.b16 {%0,%1,%2,%3}, [%4];"
        : "=r"(r[0]), "=r"(r[1]), "=r"(r[2]), "=r"(r[3]) : "r"(a));
}
__device__ __forceinline__ void ldsm4t(uint32_t* r, uint32_t a) {
    asm volatile("ldmatrix.sync.aligned.m8n8.x4.trans.shared.b16 {%0,%1,%2,%3}, [%4];"
        : "=r"(r[0]), "=r"(r[1]), "=r"(r[2]), "=r"(r[3]) : "r"(a));
}
__device__ __forceinline__ void mma_bf16(float* c, const uint32_t* a,
                                         const uint32_t* b) {
    asm volatile(
        "mma.sync.aligned.m16n8k16.row.col.f32.bf16.bf16.f32 "
        "{%0,%1,%2,%3}, {%4,%5,%6,%7}, {%8,%9}, {%0,%1,%2,%3};"
        : "+f"(c[0]), "+f"(c[1]), "+f"(c[2]), "+f"(c[3])
        : "r"(a[0]), "r"(a[1]), "r"(a[2]), "r"(a[3]), "r"(b[0]), "r"(b[1]));
}
// pack two f32 -> bf16x2 (e0 = low/element0)
__device__ __forceinline__ uint32_t packbf(float e0, float e1) {
    uint32_t r;
    asm("cvt.rn.bf16x2.f32 %0, %1, %2;" : "=r"(r) : "f"(e1), "f"(e0));
    return r;
}
// residual pack: given hi pack of (e0,e1), return bf16x2 of (e0-hi0, e1-hi1)
__device__ __forceinline__ uint32_t lopackbf(uint32_t hipack, float e0, float e1) {
    float h0 = __uint_as_float(hipack << 16);          // bf16->f32 exact
    float h1 = __uint_as_float(hipack & 0xffff0000u);
    return packbf(e0 - h0, e1 - h1);
}
__device__ __forceinline__ float ex2f(float x) {
    float y;
    asm("ex2.approx.ftz.f32 %0, %1;" : "=f"(y) : "f"(x));
    return y;
}

// ---------------------------------------------------------------------------
// Split fp32 -> (hi, lo) bf16 (elementwise)
// ---------------------------------------------------------------------------
__global__ __launch_bounds__(256)
void split_kernel(const float* __restrict__ in, __nv_bfloat16* __restrict__ hi,
                  __nv_bfloat16* __restrict__ lo, int n)
{
    int i = (blockIdx.x * 256 + threadIdx.x) * 4;
    if (i >= n) return;
    float4 v = *(const float4*)(in + i);
    uint32_t h0 = packbf(v.x, v.y);
    uint32_t h1 = packbf(v.z, v.w);
    *(uint32_t*)(hi + i)     = h0;
    *(uint32_t*)(hi + i + 2) = h1;
    *(uint32_t*)(lo + i)     = lopackbf(h0, v.x, v.y);
    *(uint32_t*)(lo + i + 2) = lopackbf(h1, v.z, v.w);
}

// ---------------------------------------------------------------------------
// Transpose + split: W fp32 [K][N] -> Whi/Wlo bf16 [N][K]
// ---------------------------------------------------------------------------
__global__ __launch_bounds__(256)
void tsplit_kernel(const float* __restrict__ W, __nv_bfloat16* __restrict__ hi,
                   __nv_bfloat16* __restrict__ lo, int K, int N)
{
    __shared__ float t[32][33];
    const int n0 = blockIdx.x * 32, k0 = blockIdx.y * 32;
    const int x = threadIdx.x & 31, y = threadIdx.x >> 5;   // y in 0..7
#pragma unroll
    for (int i = 0; i < 4; i++)
        t[y + 8 * i][x] = W[(size_t)(k0 + y + 8 * i) * N + n0 + x];
    __syncthreads();
#pragma unroll
    for (int i = 0; i < 4; i++) {
        float v = t[x][y + 8 * i];
        __nv_bfloat16 h = __float2bfloat16(v);
        size_t o = (size_t)(n0 + y + 8 * i) * K + k0 + x;
        hi[o] = h;
        lo[o] = __float2bfloat16(v - __bfloat162float(h));
    }
}

// ---------------------------------------------------------------------------
// HMMA bf16x3 GEMM: C = A @ B^T  (B stored [N][K] K-major)
// Epilogue: fp32 C (if Cf) or split bf16 hi/lo (if Chi/Clo).
// ---------------------------------------------------------------------------
#define BKC        32
#define SKB        80
#define OPB        (128 * SKB)
#define STGB       (4 * OPB)
#define GEMM_SMEM  (2 * STGB)

__device__ __forceinline__ void load_op(uint32_t dstb,
                                        const __nv_bfloat16* __restrict__ src,
                                        int r0, int k0, int K, int tid)
{
#pragma unroll
    for (int t = 0; t < 2; t++) {
        const int i = tid + t * 256;
        const int row = i >> 2, seg = i & 3;
        cpa16(dstb + (uint32_t)(row * SKB + seg * 16),
              src + (size_t)(r0 + row) * K + k0 + seg * 8);
    }
}

__device__ __forceinline__ void load_stage(
    uint32_t sbase,
    const __nv_bfloat16* __restrict__ Ahi, const __nv_bfloat16* __restrict__ Alo,
    const __nv_bfloat16* __restrict__ Bhi, const __nv_bfloat16* __restrict__ Blo,
    int m0, int n0, int k0, int K, int tid)
{
    load_op(sbase + 0 * OPB, Ahi, m0, k0, K, tid);
    load_op(sbase + 1 * OPB, Alo, m0, k0, K, tid);
    load_op(sbase + 2 * OPB, Bhi, n0, k0, K, tid);
    load_op(sbase + 3 * OPB, Blo, n0, k0, K, tid);
}

__global__ __launch_bounds__(256, 2)
void gemm_hmma(const __nv_bfloat16* __restrict__ Ahi,
               const __nv_bfloat16* __restrict__ Alo,
               const __nv_bfloat16* __restrict__ Bhi,
               const __nv_bfloat16* __restrict__ Blo,
               float* __restrict__ Cf,
               __nv_bfloat16* __restrict__ Chi,
               __nv_bfloat16* __restrict__ Clo,
               int M, int N, int K)
{
    extern __shared__ char smc[];
    const uint32_t sb = smem_u32(smc);
    const int tid  = threadIdx.x;
    const int wid  = tid >> 5, lane = tid & 31;
    const int wm   = wid >> 2;
    const int wn   = wid & 3;
    const int g    = lane >> 2;
    const int tig  = lane & 3;
    const int m0 = blockIdx.y * 128, n0 = blockIdx.x * 128;

    const int lrow  = lane & 15;
    const int lhalf = lane >> 4;
    const int brow  = (lane & 7) | ((lane & 16) >> 1);
    const int bhalf = (lane >> 3) & 1;

    float acc[4][4][4];
#pragma unroll
    for (int mt = 0; mt < 4; mt++)
#pragma unroll
        for (int nt = 0; nt < 4; nt++)
#pragma unroll
            for (int q = 0; q < 4; q++) acc[mt][nt][q] = 0.0f;

    const int NC = K / BKC;

    load_stage(sb, Ahi, Alo, Bhi, Blo, m0, n0, 0, K, tid);
    cp_commit();
    load_stage(sb + STGB, Ahi, Alo, Bhi, Blo, m0, n0, BKC, K, tid);
    cp_commit();

    for (int kc = 0; kc < NC; kc++) {
        if (kc == NC - 1) cp_wait<0>(); else cp_wait<1>();
        __syncthreads();

        const uint32_t st = sb + (uint32_t)(kc & 1) * STGB;
        const uint32_t aB = st + (uint32_t)((wm * 64 + lrow) * SKB + lhalf * 16);
        const uint32_t bB = st + 2u * OPB
                          + (uint32_t)((wn * 32 + brow) * SKB + bhalf * 16);
#pragma unroll
        for (int ks = 0; ks < 2; ks++) {
            const uint32_t kb = (uint32_t)(ks * 32);

            uint32_t bh[2][4], bl[2][4];
#pragma unroll
            for (int pr = 0; pr < 2; pr++) {
                ldsm4(bh[pr], bB + (uint32_t)(pr * 16 * SKB) + kb);
                ldsm4(bl[pr], bB + OPB + (uint32_t)(pr * 16 * SKB) + kb);
            }
#pragma unroll
            for (int mt = 0; mt < 4; mt++) {
                uint32_t ah[4], al[4];
                ldsm4(ah, aB + (uint32_t)(mt * 16 * SKB) + kb);
                ldsm4(al, aB + OPB + (uint32_t)(mt * 16 * SKB) + kb);
#pragma unroll
                for (int nt = 0; nt < 4; nt++) {
                    const uint32_t* bhp = &bh[nt >> 1][(nt & 1) * 2];
                    const uint32_t* blp = &bl[nt >> 1][(nt & 1) * 2];
                    mma_bf16(acc[mt][nt], ah, bhp);
                    mma_bf16(acc[mt][nt], ah, blp);
                    mma_bf16(acc[mt][nt], al, bhp);
                }
            }
        }
        __syncthreads();

        if (kc + 2 < NC) {
            load_stage(st, Ahi, Alo, Bhi, Blo, m0, n0, (kc + 2) * BKC, K, tid);
            cp_commit();
        }
    }

#pragma unroll
    for (int mt = 0; mt < 4; mt++) {
        const int row = m0 + wm * 64 + mt * 16 + g;
#pragma unroll
        for (int nt = 0; nt < 4; nt++) {
            const int col = n0 + wn * 32 + nt * 8 + tig * 2;
            if (Cf) {
                *(float2*)&Cf[(size_t)row * N + col] =
                    make_float2(acc[mt][nt][0], acc[mt][nt][1]);
                *(float2*)&Cf[(size_t)(row + 8) * N + col] =
                    make_float2(acc[mt][nt][2], acc[mt][nt][3]);
            } else {
                uint32_t h0 = packbf(acc[mt][nt][0], acc[mt][nt][1]);
                uint32_t h1 = packbf(acc[mt][nt][2], acc[mt][nt][3]);
                *(uint32_t*)&Chi[(size_t)row * N + col]       = h0;
                *(uint32_t*)&Chi[(size_t)(row + 8) * N + col] = h1;
                *(uint32_t*)&Clo[(size_t)row * N + col] =
                    lopackbf(h0, acc[mt][nt][0], acc[mt][nt][1]);
                *(uint32_t*)&Clo[(size_t)(row + 8) * N + col] =
                    lopackbf(h1, acc[mt][nt][2], acc[mt][nt][3]);
            }
        }
    }
}

// ---------------------------------------------------------------------------
// HMMA flash attention (causal). Block = (q-tile 64, head, batch), 128 thr.
// Q/K/V in smem as split bf16, 272B row stride (ldsm conflict-free).
// S = QhiKhi + QhiKlo + QloKhi; O += PhiVhi + PloVhi + PhiVlo.
// Softmax scale folded into ex2 argument.
// ---------------------------------------------------------------------------
#define SKVB   272                       // smem row stride bytes (136 bf16)
#define TILEB  (64 * SKVB)               // 17408 B per operand tile
#define ATTN_SMEM (6 * TILEB)            // 104448 B
#define CL2E   (0.08838834764831845f * 1.4426950408889634f)  // scale*log2(e)

__global__ __launch_bounds__(128)
void attn_mma(const __nv_bfloat16* __restrict__ qh,
              const __nv_bfloat16* __restrict__ ql,
              __nv_bfloat16* __restrict__ ohi,
              __nv_bfloat16* __restrict__ olo)
{
    extern __shared__ char sma[];
    const uint32_t sb = smem_u32(sma);
    const int qt = (int)gridDim.x - 1 - (int)blockIdx.x;   // heavy tiles first
    const int h = blockIdx.y, b = blockIdx.z;
    const int tid = threadIdx.x, lane = tid & 31, w = tid >> 5;
    const int g = lane >> 2, tig = lane & 3;
    const int lrow = lane & 15, lhalf = lane >> 4;
    const int brow = (lane & 7) | ((lane & 16) >> 1), bhalf = (lane >> 3) & 1;

    const uint32_t sQH = sb, sQL = sb + TILEB;
    const uint32_t sKH = sb + 2 * TILEB, sKL = sb + 3 * TILEB;
    const uint32_t sVH = sb + 4 * TILEB, sVL = sb + 5 * TILEB;

    const size_t qrow0 = (size_t)b * TSEQ + (size_t)qt * 64;

    // ---- load Q tile (hi/lo) ----
    {
        const __nv_bfloat16* qbh = qh + qrow0 * NQKV + h * HD;
        const __nv_bfloat16* qbl = ql + qrow0 * NQKV + h * HD;
#pragma unroll
        for (int it = 0; it < 8; it++) {
            int idx = tid + it * 128;           // 0..1023
            int r = idx >> 4, cs = idx & 15;
            uint32_t so = (uint32_t)(r * SKVB + cs * 16);
            size_t go = (size_t)r * NQKV + cs * 8;
            cpa16(sQH + so, qbh + go);
            cpa16(sQL + so, qbl + go);
        }
    }
    // ---- load K,V for kt=0 ----
    {
        const size_t kr0 = (size_t)b * TSEQ;
        const __nv_bfloat16* kh = qh + kr0 * NQKV + D_MODEL + h * HD;
        const __nv_bfloat16* kl = ql + kr0 * NQKV + D_MODEL + h * HD;
        const __nv_bfloat16* vh = qh + kr0 * NQKV + 2 * D_MODEL + h * HD;
        const __nv_bfloat16* vl = ql + kr0 * NQKV + 2 * D_MODEL + h * HD;
#pragma unroll
        for (int it = 0; it < 8; it++) {
            int idx = tid + it * 128;
            int r = idx >> 4, cs = idx & 15;
            uint32_t so = (uint32_t)(r * SKVB + cs * 16);
            size_t go = (size_t)r * NQKV + cs * 8;
            cpa16(sKH + so, kh + go); cpa16(sKL + so, kl + go);
            cpa16(sVH + so, vh + go); cpa16(sVL + so, vl + go);
        }
    }
    cp_commit();
    cp_wait<0>();
    __syncthreads();

    float o[16][4];
#pragma unroll
    for (int t = 0; t < 16; t++)
#pragma unroll
        for (int q = 0; q < 4; q++) o[t][q] = 0.0f;
    float mi0 = -1e30f, mi1 = -1e30f, li0 = 0.0f, li1 = 0.0f;

    const uint32_t aH = sQH + (uint32_t)((w * 16 + lrow) * SKVB + lhalf * 16);
    const uint32_t aL = sQL + (uint32_t)((w * 16 + lrow) * SKVB + lhalf * 16);
    const uint32_t bH = sKH + (uint32_t)(brow * SKVB + bhalf * 16);
    const uint32_t bL = sKL + (uint32_t)(brow * SKVB + bhalf * 16);
    const uint32_t vH = sVH + (uint32_t)((lane & 15) * SKVB + (lane >> 4) * 16);
    const uint32_t vL = sVL + (uint32_t)((lane & 15) * SKVB + (lane >> 4) * 16);

    for (int kt = 0; kt <= qt; kt++) {
        // ---- S = Q K^T (bf16x3), per-warp 16x64 ----
        float sc[8][4];
#pragma unroll
        for (int nt = 0; nt < 8; nt++)
#pragma unroll
            for (int q = 0; q < 4; q++) sc[nt][q] = 0.0f;

#pragma unroll
        for (int s = 0; s < 8; s++) {
            const uint32_t kb = (uint32_t)(s * 32);
            uint32_t ah[4], al[4];
            ldsm4(ah, aH + kb);
            ldsm4(al, aL + kb);
            uint32_t kh4[4][4], kl4[4][4];
#pragma unroll
            for (int p = 0; p < 4; p++) {
                ldsm4(kh4[p], bH + (uint32_t)(p * 16 * SKVB) + kb);
                ldsm4(kl4[p], bL + (uint32_t)(p * 16 * SKVB) + kb);
            }
#pragma unroll
            for (int nt = 0; nt < 8; nt++) {
                const uint32_t* bhp = &kh4[nt >> 1][(nt & 1) * 2];
                const uint32_t* blp = &kl4[nt >> 1][(nt & 1) * 2];
                mma_bf16(sc[nt], ah, bhp);
                mma_bf16(sc[nt], ah, blp);
                mma_bf16(sc[nt], al, bhp);
            }
        }

        // ---- causal mask (diagonal tile only) ----
        if (kt == qt) {
            const int r0 = w * 16 + g, r1 = r0 + 8;
#pragma unroll
            for (int nt = 0; nt < 8; nt++) {
                const int c0 = nt * 8 + 2 * tig;
                if (c0     > r0) sc[nt][0] = -1e30f;
                if (c0 + 1 > r0) sc[nt][1] = -1e30f;
                if (c0     > r1) sc[nt][2] = -1e30f;
                if (c0 + 1 > r1) sc[nt][3] = -1e30f;
            }
        }

        // ---- online softmax (scale folded into ex2) ----
        float m0 = -1e30f, m1 = -1e30f;
#pragma unroll
        for (int nt = 0; nt < 8; nt++) {
            m0 = fmaxf(m0, fmaxf(sc[nt][0], sc[nt][1]));
            m1 = fmaxf(m1, fmaxf(sc[nt][2], sc[nt][3]));
        }
        m0 = fmaxf(m0, __shfl_xor_sync(0xffffffffu, m0, 1));
        m0 = fmaxf(m0, __shfl_xor_sync(0xffffffffu, m0, 2));
        m1 = fmaxf(m1, __shfl_xor_sync(0xffffffffu, m1, 1));
        m1 = fmaxf(m1, __shfl_xor_sync(0xffffffffu, m1, 2));
        const float n0 = fmaxf(mi0, m0), n1 = fmaxf(mi1, m1);
        const float c0 = ex2f((mi0 - n0) * CL2E);
        const float c1 = ex2f((mi1 - n1) * CL2E);
        mi0 = n0; mi1 = n1;
        float r0 = 0.0f, r1 = 0.0f;
#pragma unroll
        for (int nt = 0; nt < 8; nt++) {
            sc[nt][0] = ex2f((sc[nt][0] - n0) * CL2E);
            sc[nt][1] = ex2f((sc[nt][1] - n0) * CL2E);
            sc[nt][2] = ex2f((sc[nt][2] - n1) * CL2E);
            sc[nt][3] = ex2f((sc[nt][3] - n1) * CL2E);
            r0 += sc[nt][0] + sc[nt][1];
            r1 += sc[nt][2] + sc[nt][3];
        }
        r0 += __shfl_xor_sync(0xffffffffu, r0, 1);
        r0 += __shfl_xor_sync(0xffffffffu, r0, 2);
        r1 += __shfl_xor_sync(0xffffffffu, r1, 1);
        r1 += __shfl_xor_sync(0xffffffffu, r1, 2);
        li0 = li0 * c0 + r0;
        li1 = li1 * c1 + r1;
#pragma unroll
        for (int t = 0; t < 16; t++) {
            o[t][0] *= c0; o[t][1] *= c0;
            o[t][2] *= c1; o[t][3] *= c1;
        }

        // ---- O += P V (bf16x3; P split is exact) ----
#pragma unroll
        for (int s = 0; s < 4; s++) {
            uint32_t phi[4], plo[4];
            phi[0] = packbf(sc[2*s][0],   sc[2*s][1]);
            phi[1] = packbf(sc[2*s][2],   sc[2*s][3]);
            phi[2] = packbf(sc[2*s+1][0], sc[2*s+1][1]);
            phi[3] = packbf(sc[2*s+1][2], sc[2*s+1][3]);
            plo[0] = lopackbf(phi[0], sc[2*s][0],   sc[2*s][1]);
            plo[1] = lopackbf(phi[1], sc[2*s][2],   sc[2*s][3]);
            plo[2] = lopackbf(phi[2], sc[2*s+1][0], sc[2*s+1][1]);
            plo[3] = lopackbf(phi[3], sc[2*s+1][2], sc[2*s+1][3]);

            const uint32_t vrow = (uint32_t)(s * 16 * SKVB);
#pragma unroll
            for (int p = 0; p < 8; p++) {
                uint32_t vh4[4], vl4[4];
                ldsm4t(vh4, vH + vrow + (uint32_t)(p * 32));
                ldsm4t(vl4, vL + vrow + (uint32_t)(p * 32));
                mma_bf16(o[2*p],   phi, &vh4[0]);
                mma_bf16(o[2*p],   plo, &vh4[0]);
                mma_bf16(o[2*p],   phi, &vl4[0]);
                mma_bf16(o[2*p+1], phi, &vh4[2]);
                mma_bf16(o[2*p+1], plo, &vh4[2]);
                mma_bf16(o[2*p+1], phi, &vl4[2]);
            }
        }

        // ---- prefetch next K/V ----
        if (kt < qt) {
            __syncthreads();
            const size_t kr0 = (size_t)b * TSEQ + (size_t)(kt + 1) * 64;
            const __nv_bfloat16* kh = qh + kr0 * NQKV + D_MODEL + h * HD;
            const __nv_bfloat16* kl = ql + kr0 * NQKV + D_MODEL + h * HD;
            const __nv_bfloat16* vh = qh + kr0 * NQKV + 2 * D_MODEL + h * HD;
            const __nv_bfloat16* vl = ql + kr0 * NQKV + 2 * D_MODEL + h * HD;
#pragma unroll
            for (int it = 0; it < 8; it++) {
                int idx = tid + it * 128;
                int r = idx >> 4, cs = idx & 15;
                uint32_t so = (uint32_t)(r * SKVB + cs * 16);
                size_t go = (size_t)r * NQKV + cs * 8;
                cpa16(sKH + so, kh + go); cpa16(sKL + so, kl + go);
                cpa16(sVH + so, vh + go); cpa16(sVL + so, vl + go);
            }
            cp_commit();
            cp_wait<0>();
            __syncthreads();
        }
    }

    // ---- epilogue: normalize, split bf16 hi/lo ----
    const float inv0 = 1.0f / li0, inv1 = 1.0f / li1;
    const size_t row0 = qrow0 + w * 16 + g, row1 = row0 + 8;
#pragma unroll
    for (int nt = 0; nt < 16; nt++) {
        const int col = h * HD + nt * 8 + 2 * tig;
        float a0 = o[nt][0] * inv0, a1 = o[nt][1] * inv0;
        float a2 = o[nt][2] * inv1, a3 = o[nt][3] * inv1;
        uint32_t h0 = packbf(a0, a1), h1 = packbf(a2, a3);
        *(uint32_t*)&ohi[row0 * D_MODEL + col] = h0;
        *(uint32_t*)&ohi[row1 * D_MODEL + col] = h1;
        *(uint32_t*)&olo[row0 * D_MODEL + col] = lopackbf(h0, a0, a1);
        *(uint32_t*)&olo[row1 * D_MODEL + col] = lopackbf(h1, a2, a3);
    }
}

// ---------------------------------------------------------------------------
extern "C" void kernel_launch(void* const* d_in, const int* in_sizes, int n_in,
                              void* d_out, int out_size)
{
    (void)in_sizes; (void)n_in; (void)out_size;
    const float* x      = (const float*)d_in[0];
    const float* w_qkv  = (const float*)d_in[1];
    const float* w_proj = (const float*)d_in[2];
    float* out = (float*)d_out;

    __nv_bfloat16 *qhi, *qlo, *xhi, *xlo, *ahi, *alo, *wqhi, *wqlo, *wphi, *wplo;
    cudaGetSymbolAddress((void**)&qhi,  g_qkvhi);
    cudaGetSymbolAddress((void**)&qlo,  g_qkvlo);
    cudaGetSymbolAddress((void**)&xhi,  g_xhi);
    cudaGetSymbolAddress((void**)&xlo,  g_xlo);
    cudaGetSymbolAddress((void**)&ahi,  g_ahi);
    cudaGetSymbolAddress((void**)&alo,  g_alo);
    cudaGetSymbolAddress((void**)&wqhi, g_wqhi);
    cudaGetSymbolAddress((void**)&wqlo, g_wqlo);
    cudaGetSymbolAddress((void**)&wphi, g_wphi);
    cudaGetSymbolAddress((void**)&wplo, g_wplo);

    cudaFuncSetAttribute(gemm_hmma,
                         cudaFuncAttributeMaxDynamicSharedMemorySize, GEMM_SMEM);
    cudaFuncSetAttribute(attn_mma,
                         cudaFuncAttributeMaxDynamicSharedMemorySize, ATTN_SMEM);

    const int nx = MTOT * D_MODEL;

    // 1) split x -> bf16 hi/lo
    split_kernel<<<nx / 4 / 256, 256>>>(x, xhi, xlo, nx);
    // 2) transpose+split weights -> [N][K] bf16 hi/lo
    tsplit_kernel<<<dim3(NQKV / 32, D_MODEL / 32), 256>>>(w_qkv, wqhi, wqlo,
                                                          D_MODEL, NQKV);
    tsplit_kernel<<<dim3(D_MODEL / 32, D_MODEL / 32), 256>>>(w_proj, wphi, wplo,
                                                             D_MODEL, D_MODEL);
    // 3) qkv = x @ w_qkv  -> split bf16 hi/lo directly
    gemm_hmma<<<dim3(NQKV / 128, MTOT / 128), 256, GEMM_SMEM>>>(
        xhi, xlo, wqhi, wqlo, nullptr, qhi, qlo, MTOT, NQKV, D_MODEL);
    // 4) HMMA flash attention -> split bf16 hi/lo
    attn_mma<<<dim3(TSEQ / 64, NHEAD, BATCH), 128, ATTN_SMEM>>>(
        qhi, qlo, ahi, alo);
    // 5) out = att @ w_proj (fp32 out)
    gemm_hmma<<<dim3(D_MODEL / 128, MTOT / 128), 256, GEMM_SMEM>>>(
        ahi, alo, wphi, wplo, out, nullptr, nullptr, MTOT, D_MODEL, D_MODEL);
}

// round 8
// speedup vs baseline: 2.9489x; 1.1149x over previous
#include <cuda_runtime.h>
#include <cuda_bf16.h>
#include <cstdint>

#define D_MODEL 2048
#define NHEAD   16
#define HD      128
#define TSEQ    1024
#define BATCH   4
#define MTOT    (BATCH * TSEQ)     // 4096
#define NQKV    (3 * D_MODEL)      // 6144

// ---------------------------------------------------------------------------
// Scratch (__device__ globals — allocation-guard safe), 16B-aligned
// ---------------------------------------------------------------------------
__device__ __align__(16) __nv_bfloat16 g_qkvhi[MTOT * NQKV];
__device__ __align__(16) __nv_bfloat16 g_qkvlo[MTOT * NQKV];
__device__ __align__(16) __nv_bfloat16 g_xhi[MTOT * D_MODEL];
__device__ __align__(16) __nv_bfloat16 g_xlo[MTOT * D_MODEL];
__device__ __align__(16) __nv_bfloat16 g_ahi[MTOT * D_MODEL];
__device__ __align__(16) __nv_bfloat16 g_alo[MTOT * D_MODEL];
__device__ __align__(16) __nv_bfloat16 g_wqhi[NQKV * D_MODEL];
__device__ __align__(16) __nv_bfloat16 g_wqlo[NQKV * D_MODEL];
__device__ __align__(16) __nv_bfloat16 g_wphi[D_MODEL * D_MODEL];
__device__ __align__(16) __nv_bfloat16 g_wplo[D_MODEL * D_MODEL];

// ---------------------------------------------------------------------------
// helpers
// ---------------------------------------------------------------------------
__device__ __forceinline__ uint32_t smem_u32(const void* p) {
    uint32_t a;
    asm("{ .reg .u64 t; cvta.to.shared.u64 t, %1; cvt.u32.u64 %0, t; }"
        : "=r"(a) : "l"(p));
    return a;
}
__device__ __forceinline__ void cpa16(uint32_t dst, const void* src) {
    asm volatile("cp.async.cg.shared.global [%0], [%1], 16;" :: "r"(dst), "l"(src));
}
__device__ __forceinline__ void cp_commit() { asm volatile("cp.async.commit_group;"); }
template <int N> __device__ __forceinline__ void cp_wait() {
    asm volatile("cp.async.wait_group %0;" :: "n"(N));
}
__device__ __forceinline__ void ldsm4(uint32_t* r, uint32_t a) {
    asm volatile("ldmatrix.sync.aligned.m8n8.x4.shared.b16 {%0,%1,%2,%3}, [%4];"
        : "=r"(r[0]), "=r"(r[1]), "=r"(r[2]), "=r"(r[3]) : "r"(a));
}
__device__ __forceinline__ void ldsm4t(uint32_t* r, uint32_t a) {
    asm volatile("ldmatrix.sync.aligned.m8n8.x4.trans.shared.b16 {%0,%1,%2,%3}, [%4];"
        : "=r"(r[0]), "=r"(r[1]), "=r"(r[2]), "=r"(r[3]) : "r"(a));
}
__device__ __forceinline__ void mma_bf16(float* c, const uint32_t* a,
                                         const uint32_t* b) {
    asm volatile(
        "mma.sync.aligned.m16n8k16.row.col.f32.bf16.bf16.f32 "
        "{%0,%1,%2,%3}, {%4,%5,%6,%7}, {%8,%9}, {%0,%1,%2,%3};"
        : "+f"(c[0]), "+f"(c[1]), "+f"(c[2]), "+f"(c[3])
        : "r"(a[0]), "r"(a[1]), "r"(a[2]), "r"(a[3]), "r"(b[0]), "r"(b[1]));
}
__device__ __forceinline__ uint32_t packbf(float e0, float e1) {
    uint32_t r;
    asm("cvt.rn.bf16x2.f32 %0, %1, %2;" : "=r"(r) : "f"(e1), "f"(e0));
    return r;
}
__device__ __forceinline__ uint32_t lopackbf(uint32_t hipack, float e0, float e1) {
    float h0 = __uint_as_float(hipack << 16);
    float h1 = __uint_as_float(hipack & 0xffff0000u);
    return packbf(e0 - h0, e1 - h1);
}
__device__ __forceinline__ float ex2f(float x) {
    float y;
    asm("ex2.approx.ftz.f32 %0, %1;" : "=f"(y) : "f"(x));
    return y;
}
// 64B-row swizzle: bits [4:5] ^= bits [7:8]. Must be applied to the FULL
// sub-bit-10 logical offset (row%16, k-byte) — adds of multiples of 1024
// commute with it; adds of 32 do NOT (bit-5 carry).
__device__ __forceinline__ uint32_t swz(uint32_t off) {
    return off ^ (((off >> 7) & 3u) << 4);
}

// ---------------------------------------------------------------------------
// Split fp32 -> (hi, lo) bf16 (elementwise)
// ---------------------------------------------------------------------------
__global__ __launch_bounds__(256)
void split_kernel(const float* __restrict__ in, __nv_bfloat16* __restrict__ hi,
                  __nv_bfloat16* __restrict__ lo, int n)
{
    int i = (blockIdx.x * 256 + threadIdx.x) * 4;
    if (i >= n) return;
    float4 v = *(const float4*)(in + i);
    uint32_t h0 = packbf(v.x, v.y);
    uint32_t h1 = packbf(v.z, v.w);
    *(uint32_t*)(hi + i)     = h0;
    *(uint32_t*)(hi + i + 2) = h1;
    *(uint32_t*)(lo + i)     = lopackbf(h0, v.x, v.y);
    *(uint32_t*)(lo + i + 2) = lopackbf(h1, v.z, v.w);
}

// ---------------------------------------------------------------------------
// Transpose + split: W fp32 [K][N] -> Whi/Wlo bf16 [N][K]
// ---------------------------------------------------------------------------
__global__ __launch_bounds__(256)
void tsplit_kernel(const float* __restrict__ W, __nv_bfloat16* __restrict__ hi,
                   __nv_bfloat16* __restrict__ lo, int K, int N)
{
    __shared__ float t[32][33];
    const int n0 = blockIdx.x * 32, k0 = blockIdx.y * 32;
    const int x = threadIdx.x & 31, y = threadIdx.x >> 5;
#pragma unroll
    for (int i = 0; i < 4; i++)
        t[y + 8 * i][x] = W[(size_t)(k0 + y + 8 * i) * N + n0 + x];
    __syncthreads();
#pragma unroll
    for (int i = 0; i < 4; i++) {
        float v = t[x][y + 8 * i];
        __nv_bfloat16 h = __float2bfloat16(v);
        size_t o = (size_t)(n0 + y + 8 * i) * K + k0 + x;
        hi[o] = h;
        lo[o] = __float2bfloat16(v - __bfloat162float(h));
    }
}

// ---------------------------------------------------------------------------
// HMMA bf16x3 GEMM: C = A @ B^T  (B stored [N][K] K-major)
// 128x128 tile, BK=32, 8 warps, 3-stage cp.async pipeline, swizzled smem.
// Prefetch issued BEFORE compute. Per-ks swizzled fragment bases (the k-step
// is folded into the offset BEFORE the swizzle — bit-5 carry bug fix).
// ---------------------------------------------------------------------------
#define BKC        32
#define OPB        (128 * 64)               // 8192 B per operand tile
#define STGB       (4 * OPB)                // 32768 B per stage
#define NSTG       3
#define GEMM_SMEM  (NSTG * STGB)            // 98304 B

__device__ __forceinline__ void load_op(uint32_t dstb,
                                        const __nv_bfloat16* __restrict__ src,
                                        int r0, int k0, int K, int tid)
{
#pragma unroll
    for (int t = 0; t < 2; t++) {
        const int i = tid + t * 256;        // 0..511
        const int row = i >> 2, seg = i & 3;
        cpa16(dstb + swz((uint32_t)(row * 64 + seg * 16)),
              src + (size_t)(r0 + row) * K + k0 + seg * 8);
    }
}

__device__ __forceinline__ void load_stage(
    uint32_t sbase,
    const __nv_bfloat16* __restrict__ Ahi, const __nv_bfloat16* __restrict__ Alo,
    const __nv_bfloat16* __restrict__ Bhi, const __nv_bfloat16* __restrict__ Blo,
    int m0, int n0, int k0, int K, int tid)
{
    load_op(sbase + 0 * OPB, Ahi, m0, k0, K, tid);
    load_op(sbase + 1 * OPB, Alo, m0, k0, K, tid);
    load_op(sbase + 2 * OPB, Bhi, n0, k0, K, tid);
    load_op(sbase + 3 * OPB, Blo, n0, k0, K, tid);
}

__global__ __launch_bounds__(256, 2)
void gemm_hmma(const __nv_bfloat16* __restrict__ Ahi,
               const __nv_bfloat16* __restrict__ Alo,
               const __nv_bfloat16* __restrict__ Bhi,
               const __nv_bfloat16* __restrict__ Blo,
               float* __restrict__ Cf,
               __nv_bfloat16* __restrict__ Chi,
               __nv_bfloat16* __restrict__ Clo,
               int M, int N, int K)
{
    extern __shared__ char smc[];
    const uint32_t sb = smem_u32(smc);
    const int tid  = threadIdx.x;
    const int wid  = tid >> 5, lane = tid & 31;
    const int wm   = wid >> 2;
    const int wn   = wid & 3;
    const int g    = lane >> 2;
    const int tig  = lane & 3;
    const int m0 = blockIdx.y * 128, n0 = blockIdx.x * 128;

    const int lrow  = lane & 15;
    const int lhalf = lane >> 4;
    const int brow  = (lane & 7) | ((lane & 16) >> 1);
    const int bhalf = (lane >> 3) & 1;

    // per-ks swizzled fragment bases (k-step folded in pre-swizzle; the
    // remaining runtime adds are multiples of 1024 which commute with swz)
    uint32_t aoff[2], boff[2];
#pragma unroll
    for (int ks = 0; ks < 2; ks++) {
        aoff[ks] = swz((uint32_t)((wm * 64 + lrow) * 64 + lhalf * 16 + ks * 32));
        boff[ks] = swz((uint32_t)((wn * 32 + brow) * 64 + bhalf * 16 + ks * 32));
    }

    float acc[4][4][4];
#pragma unroll
    for (int mt = 0; mt < 4; mt++)
#pragma unroll
        for (int nt = 0; nt < 4; nt++)
#pragma unroll
            for (int q = 0; q < 4; q++) acc[mt][nt][q] = 0.0f;

    const int NC = K / BKC;

    load_stage(sb, Ahi, Alo, Bhi, Blo, m0, n0, 0, K, tid);
    cp_commit();
    load_stage(sb + STGB, Ahi, Alo, Bhi, Blo, m0, n0, BKC, K, tid);
    cp_commit();

    int st_idx = 0;
    for (int kc = 0; kc < NC; kc++) {
        if (kc + 1 < NC) cp_wait<1>(); else cp_wait<0>();
        __syncthreads();   // chunk kc visible to all warps

        // early prefetch: chunk kc+2 into stage (kc+2)%3 (last read at kc-1)
        if (kc + 2 < NC) {
            int nst = st_idx + 2; if (nst >= NSTG) nst -= NSTG;
            load_stage(sb + (uint32_t)nst * STGB,
                       Ahi, Alo, Bhi, Blo, m0, n0, (kc + 2) * BKC, K, tid);
            cp_commit();
        }

        const uint32_t st = sb + (uint32_t)st_idx * STGB;
#pragma unroll
        for (int ks = 0; ks < 2; ks++) {
            const uint32_t aB = st + aoff[ks];
            const uint32_t bB = st + 2u * OPB + boff[ks];

            uint32_t bh[2][4], bl[2][4];
#pragma unroll
            for (int pr = 0; pr < 2; pr++) {
                ldsm4(bh[pr], bB + (uint32_t)(pr * 1024));
                ldsm4(bl[pr], bB + OPB + (uint32_t)(pr * 1024));
            }
#pragma unroll
            for (int mt = 0; mt < 4; mt++) {
                uint32_t ah[4], al[4];
                ldsm4(ah, aB + (uint32_t)(mt * 1024));
                ldsm4(al, aB + OPB + (uint32_t)(mt * 1024));
#pragma unroll
                for (int nt = 0; nt < 4; nt++) {
                    const uint32_t* bhp = &bh[nt >> 1][(nt & 1) * 2];
                    const uint32_t* blp = &bl[nt >> 1][(nt & 1) * 2];
                    mma_bf16(acc[mt][nt], ah, bhp);
                    mma_bf16(acc[mt][nt], ah, blp);
                    mma_bf16(acc[mt][nt], al, bhp);
                }
            }
        }
        __syncthreads();   // all reads of chunk kc retired
        if (++st_idx == NSTG) st_idx = 0;
    }

#pragma unroll
    for (int mt = 0; mt < 4; mt++) {
        const int row = m0 + wm * 64 + mt * 16 + g;
#pragma unroll
        for (int nt = 0; nt < 4; nt++) {
            const int col = n0 + wn * 32 + nt * 8 + tig * 2;
            if (Cf) {
                *(float2*)&Cf[(size_t)row * N + col] =
                    make_float2(acc[mt][nt][0], acc[mt][nt][1]);
                *(float2*)&Cf[(size_t)(row + 8) * N + col] =
                    make_float2(acc[mt][nt][2], acc[mt][nt][3]);
            } else {
                uint32_t h0 = packbf(acc[mt][nt][0], acc[mt][nt][1]);
                uint32_t h1 = packbf(acc[mt][nt][2], acc[mt][nt][3]);
                *(uint32_t*)&Chi[(size_t)row * N + col]       = h0;
                *(uint32_t*)&Chi[(size_t)(row + 8) * N + col] = h1;
                *(uint32_t*)&Clo[(size_t)row * N + col] =
                    lopackbf(h0, acc[mt][nt][0], acc[mt][nt][1]);
                *(uint32_t*)&Clo[(size_t)(row + 8) * N + col] =
                    lopackbf(h1, acc[mt][nt][2], acc[mt][nt][3]);
            }
        }
    }
}

// ---------------------------------------------------------------------------
// HMMA flash attention (causal) — unchanged from round 5 (passing)
// ---------------------------------------------------------------------------
#define SKVB   272
#define TILEB  (64 * SKVB)
#define ATTN_SMEM (6 * TILEB)
#define CL2E   (0.08838834764831845f * 1.4426950408889634f)

__global__ __launch_bounds__(128)
void attn_mma(const __nv_bfloat16* __restrict__ qh,
              const __nv_bfloat16* __restrict__ ql,
              __nv_bfloat16* __restrict__ ohi,
              __nv_bfloat16* __restrict__ olo)
{
    extern __shared__ char sma[];
    const uint32_t sb = smem_u32(sma);
    const int qt = (int)gridDim.x - 1 - (int)blockIdx.x;
    const int h = blockIdx.y, b = blockIdx.z;
    const int tid = threadIdx.x, lane = tid & 31, w = tid >> 5;
    const int g = lane >> 2, tig = lane & 3;
    const int lrow = lane & 15, lhalf = lane >> 4;
    const int brow = (lane & 7) | ((lane & 16) >> 1), bhalf = (lane >> 3) & 1;

    const uint32_t sQH = sb, sQL = sb + TILEB;
    const uint32_t sKH = sb + 2 * TILEB, sKL = sb + 3 * TILEB;
    const uint32_t sVH = sb + 4 * TILEB, sVL = sb + 5 * TILEB;

    const size_t qrow0 = (size_t)b * TSEQ + (size_t)qt * 64;

    {
        const __nv_bfloat16* qbh = qh + qrow0 * NQKV + h * HD;
        const __nv_bfloat16* qbl = ql + qrow0 * NQKV + h * HD;
#pragma unroll
        for (int it = 0; it < 8; it++) {
            int idx = tid + it * 128;
            int r = idx >> 4, cs = idx & 15;
            uint32_t so = (uint32_t)(r * SKVB + cs * 16);
            size_t go = (size_t)r * NQKV + cs * 8;
            cpa16(sQH + so, qbh + go);
            cpa16(sQL + so, qbl + go);
        }
    }
    {
        const size_t kr0 = (size_t)b * TSEQ;
        const __nv_bfloat16* kh = qh + kr0 * NQKV + D_MODEL + h * HD;
        const __nv_bfloat16* kl = ql + kr0 * NQKV + D_MODEL + h * HD;
        const __nv_bfloat16* vh = qh + kr0 * NQKV + 2 * D_MODEL + h * HD;
        const __nv_bfloat16* vl = ql + kr0 * NQKV + 2 * D_MODEL + h * HD;
#pragma unroll
        for (int it = 0; it < 8; it++) {
            int idx = tid + it * 128;
            int r = idx >> 4, cs = idx & 15;
            uint32_t so = (uint32_t)(r * SKVB + cs * 16);
            size_t go = (size_t)r * NQKV + cs * 8;
            cpa16(sKH + so, kh + go); cpa16(sKL + so, kl + go);
            cpa16(sVH + so, vh + go); cpa16(sVL + so, vl + go);
        }
    }
    cp_commit();
    cp_wait<0>();
    __syncthreads();

    float o[16][4];
#pragma unroll
    for (int t = 0; t < 16; t++)
#pragma unroll
        for (int q = 0; q < 4; q++) o[t][q] = 0.0f;
    float mi0 = -1e30f, mi1 = -1e30f, li0 = 0.0f, li1 = 0.0f;

    const uint32_t aH = sQH + (uint32_t)((w * 16 + lrow) * SKVB + lhalf * 16);
    const uint32_t aL = sQL + (uint32_t)((w * 16 + lrow) * SKVB + lhalf * 16);
    const uint32_t bH = sKH + (uint32_t)(brow * SKVB + bhalf * 16);
    const uint32_t bL = sKL + (uint32_t)(brow * SKVB + bhalf * 16);
    const uint32_t vH = sVH + (uint32_t)((lane & 15) * SKVB + (lane >> 4) * 16);
    const uint32_t vL = sVL + (uint32_t)((lane & 15) * SKVB + (lane >> 4) * 16);

    for (int kt = 0; kt <= qt; kt++) {
        float sc[8][4];
#pragma unroll
        for (int nt = 0; nt < 8; nt++)
#pragma unroll
            for (int q = 0; q < 4; q++) sc[nt][q] = 0.0f;

#pragma unroll
        for (int s = 0; s < 8; s++) {
            const uint32_t kb = (uint32_t)(s * 32);
            uint32_t ah[4], al[4];
            ldsm4(ah, aH + kb);
            ldsm4(al, aL + kb);
            uint32_t kh4[4][4], kl4[4][4];
#pragma unroll
            for (int p = 0; p < 4; p++) {
                ldsm4(kh4[p], bH + (uint32_t)(p * 16 * SKVB) + kb);
                ldsm4(kl4[p], bL + (uint32_t)(p * 16 * SKVB) + kb);
            }
#pragma unroll
            for (int nt = 0; nt < 8; nt++) {
                const uint32_t* bhp = &kh4[nt >> 1][(nt & 1) * 2];
                const uint32_t* blp = &kl4[nt >> 1][(nt & 1) * 2];
                mma_bf16(sc[nt], ah, bhp);
                mma_bf16(sc[nt], ah, blp);
                mma_bf16(sc[nt], al, bhp);
            }
        }

        if (kt == qt) {
            const int r0 = w * 16 + g, r1 = r0 + 8;
#pragma unroll
            for (int nt = 0; nt < 8; nt++) {
                const int c0 = nt * 8 + 2 * tig;
                if (c0     > r0) sc[nt][0] = -1e30f;
                if (c0 + 1 > r0) sc[nt][1] = -1e30f;
                if (c0     > r1) sc[nt][2] = -1e30f;
                if (c0 + 1 > r1) sc[nt][3] = -1e30f;
            }
        }

        float m0 = -1e30f, m1 = -1e30f;
#pragma unroll
        for (int nt = 0; nt < 8; nt++) {
            m0 = fmaxf(m0, fmaxf(sc[nt][0], sc[nt][1]));
            m1 = fmaxf(m1, fmaxf(sc[nt][2], sc[nt][3]));
        }
        m0 = fmaxf(m0, __shfl_xor_sync(0xffffffffu, m0, 1));
        m0 = fmaxf(m0, __shfl_xor_sync(0xffffffffu, m0, 2));
        m1 = fmaxf(m1, __shfl_xor_sync(0xffffffffu, m1, 1));
        m1 = fmaxf(m1, __shfl_xor_sync(0xffffffffu, m1, 2));
        const float n0 = fmaxf(mi0, m0), n1 = fmaxf(mi1, m1);
        const float c0 = ex2f((mi0 - n0) * CL2E);
        const float c1 = ex2f((mi1 - n1) * CL2E);
        mi0 = n0; mi1 = n1;
        float r0 = 0.0f, r1 = 0.0f;
#pragma unroll
        for (int nt = 0; nt < 8; nt++) {
            sc[nt][0] = ex2f((sc[nt][0] - n0) * CL2E);
            sc[nt][1] = ex2f((sc[nt][1] - n0) * CL2E);
            sc[nt][2] = ex2f((sc[nt][2] - n1) * CL2E);
            sc[nt][3] = ex2f((sc[nt][3] - n1) * CL2E);
            r0 += sc[nt][0] + sc[nt][1];
            r1 += sc[nt][2] + sc[nt][3];
        }
        r0 += __shfl_xor_sync(0xffffffffu, r0, 1);
        r0 += __shfl_xor_sync(0xffffffffu, r0, 2);
        r1 += __shfl_xor_sync(0xffffffffu, r1, 1);
        r1 += __shfl_xor_sync(0xffffffffu, r1, 2);
        li0 = li0 * c0 + r0;
        li1 = li1 * c1 + r1;
#pragma unroll
        for (int t = 0; t < 16; t++) {
            o[t][0] *= c0; o[t][1] *= c0;
            o[t][2] *= c1; o[t][3] *= c1;
        }

#pragma unroll
        for (int s = 0; s < 4; s++) {
            uint32_t phi[4], plo[4];
            phi[0] = packbf(sc[2*s][0],   sc[2*s][1]);
            phi[1] = packbf(sc[2*s][2],   sc[2*s][3]);
            phi[2] = packbf(sc[2*s+1][0], sc[2*s+1][1]);
            phi[3] = packbf(sc[2*s+1][2], sc[2*s+1][3]);
            plo[0] = lopackbf(phi[0], sc[2*s][0],   sc[2*s][1]);
            plo[1] = lopackbf(phi[1], sc[2*s][2],   sc[2*s][3]);
            plo[2] = lopackbf(phi[2], sc[2*s+1][0], sc[2*s+1][1]);
            plo[3] = lopackbf(phi[3], sc[2*s+1][2], sc[2*s+1][3]);

            const uint32_t vrow = (uint32_t)(s * 16 * SKVB);
#pragma unroll
            for (int p = 0; p < 8; p++) {
                uint32_t vh4[4], vl4[4];
                ldsm4t(vh4, vH + vrow + (uint32_t)(p * 32));
                ldsm4t(vl4, vL + vrow + (uint32_t)(p * 32));
                mma_bf16(o[2*p],   phi, &vh4[0]);
                mma_bf16(o[2*p],   plo, &vh4[0]);
                mma_bf16(o[2*p],   phi, &vl4[0]);
                mma_bf16(o[2*p+1], phi, &vh4[2]);
                mma_bf16(o[2*p+1], plo, &vh4[2]);
                mma_bf16(o[2*p+1], phi, &vl4[2]);
            }
        }

        if (kt < qt) {
            __syncthreads();
            const size_t kr0 = (size_t)b * TSEQ + (size_t)(kt + 1) * 64;
            const __nv_bfloat16* kh = qh + kr0 * NQKV + D_MODEL + h * HD;
            const __nv_bfloat16* kl = ql + kr0 * NQKV + D_MODEL + h * HD;
            const __nv_bfloat16* vh = qh + kr0 * NQKV + 2 * D_MODEL + h * HD;
            const __nv_bfloat16* vl = ql + kr0 * NQKV + 2 * D_MODEL + h * HD;
#pragma unroll
            for (int it = 0; it < 8; it++) {
                int idx = tid + it * 128;
                int r = idx >> 4, cs = idx & 15;
                uint32_t so = (uint32_t)(r * SKVB + cs * 16);
                size_t go = (size_t)r * NQKV + cs * 8;
                cpa16(sKH + so, kh + go); cpa16(sKL + so, kl + go);
                cpa16(sVH + so, vh + go); cpa16(sVL + so, vl + go);
            }
            cp_commit();
            cp_wait<0>();
            __syncthreads();
        }
    }

    const float inv0 = 1.0f / li0, inv1 = 1.0f / li1;
    const size_t row0 = qrow0 + w * 16 + g, row1 = row0 + 8;
#pragma unroll
    for (int nt = 0; nt < 16; nt++) {
        const int col = h * HD + nt * 8 + 2 * tig;
        float a0 = o[nt][0] * inv0, a1 = o[nt][1] * inv0;
        float a2 = o[nt][2] * inv1, a3 = o[nt][3] * inv1;
        uint32_t h0 = packbf(a0, a1), h1 = packbf(a2, a3);
        *(uint32_t*)&ohi[row0 * D_MODEL + col] = h0;
        *(uint32_t*)&ohi[row1 * D_MODEL + col] = h1;
        *(uint32_t*)&olo[row0 * D_MODEL + col] = lopackbf(h0, a0, a1);
        *(uint32_t*)&olo[row1 * D_MODEL + col] = lopackbf(h1, a2, a3);
    }
}

// ---------------------------------------------------------------------------
extern "C" void kernel_launch(void* const* d_in, const int* in_sizes, int n_in,
                              void* d_out, int out_size)
{
    (void)in_sizes; (void)n_in; (void)out_size;
    const float* x      = (const float*)d_in[0];
    const float* w_qkv  = (const float*)d_in[1];
    const float* w_proj = (const float*)d_in[2];
    float* out = (float*)d_out;

    __nv_bfloat16 *qhi, *qlo, *xhi, *xlo, *ahi, *alo, *wqhi, *wqlo, *wphi, *wplo;
    cudaGetSymbolAddress((void**)&qhi,  g_qkvhi);
    cudaGetSymbolAddress((void**)&qlo,  g_qkvlo);
    cudaGetSymbolAddress((void**)&xhi,  g_xhi);
    cudaGetSymbolAddress((void**)&xlo,  g_xlo);
    cudaGetSymbolAddress((void**)&ahi,  g_ahi);
    cudaGetSymbolAddress((void**)&alo,  g_alo);
    cudaGetSymbolAddress((void**)&wqhi, g_wqhi);
    cudaGetSymbolAddress((void**)&wqlo, g_wqlo);
    cudaGetSymbolAddress((void**)&wphi, g_wphi);
    cudaGetSymbolAddress((void**)&wplo, g_wplo);

    cudaFuncSetAttribute(gemm_hmma,
                         cudaFuncAttributeMaxDynamicSharedMemorySize, GEMM_SMEM);
    cudaFuncSetAttribute(attn_mma,
                         cudaFuncAttributeMaxDynamicSharedMemorySize, ATTN_SMEM);

    const int nx = MTOT * D_MODEL;

    split_kernel<<<nx / 4 / 256, 256>>>(x, xhi, xlo, nx);
    tsplit_kernel<<<dim3(NQKV / 32, D_MODEL / 32), 256>>>(w_qkv, wqhi, wqlo,
                                                          D_MODEL, NQKV);
    tsplit_kernel<<<dim3(D_MODEL / 32, D_MODEL / 32), 256>>>(w_proj, wphi, wplo,
                                                             D_MODEL, D_MODEL);
    gemm_hmma<<<dim3(NQKV / 128, MTOT / 128), 256, GEMM_SMEM>>>(
        xhi, xlo, wqhi, wqlo, nullptr, qhi, qlo, MTOT, NQKV, D_MODEL);
    attn_mma<<<dim3(TSEQ / 64, NHEAD, BATCH), 128, ATTN_SMEM>>>(
        qhi, qlo, ahi, alo);
    gemm_hmma<<<dim3(D_MODEL / 128, MTOT / 128), 256, GEMM_SMEM>>>(
        ahi, alo, wphi, wplo, out, nullptr, nullptr, MTOT, D_MODEL, D_MODEL);
}

// round 9
// speedup vs baseline: 2.9824x; 1.0114x over previous
#include <cuda_runtime.h>
#include <cuda_bf16.h>
#include <cstdint>

#define D_MODEL 2048
#define NHEAD   16
#define HD      128
#define TSEQ    1024
#define BATCH   4
#define MTOT    (BATCH * TSEQ)     // 4096
#define NQKV    (3 * D_MODEL)      // 6144

// ---------------------------------------------------------------------------
// Scratch (__device__ globals — allocation-guard safe), 16B-aligned
// ---------------------------------------------------------------------------
__device__ __align__(16) __nv_bfloat16 g_qkvhi[MTOT * NQKV];
__device__ __align__(16) __nv_bfloat16 g_qkvlo[MTOT * NQKV];
__device__ __align__(16) __nv_bfloat16 g_xhi[MTOT * D_MODEL];
__device__ __align__(16) __nv_bfloat16 g_xlo[MTOT * D_MODEL];
__device__ __align__(16) __nv_bfloat16 g_ahi[MTOT * D_MODEL];
__device__ __align__(16) __nv_bfloat16 g_alo[MTOT * D_MODEL];
__device__ __align__(16) __nv_bfloat16 g_wqhi[NQKV * D_MODEL];
__device__ __align__(16) __nv_bfloat16 g_wqlo[NQKV * D_MODEL];
__device__ __align__(16) __nv_bfloat16 g_wphi[D_MODEL * D_MODEL];
__device__ __align__(16) __nv_bfloat16 g_wplo[D_MODEL * D_MODEL];

// ---------------------------------------------------------------------------
// helpers
// ---------------------------------------------------------------------------
__device__ __forceinline__ uint32_t smem_u32(const void* p) {
    uint32_t a;
    asm("{ .reg .u64 t; cvta.to.shared.u64 t, %1; cvt.u32.u64 %0, t; }"
        : "=r"(a) : "l"(p));
    return a;
}
__device__ __forceinline__ void cpa16(uint32_t dst, const void* src) {
    asm volatile("cp.async.cg.shared.global [%0], [%1], 16;" :: "r"(dst), "l"(src));
}
__device__ __forceinline__ void cp_commit() { asm volatile("cp.async.commit_group;"); }
template <int N> __device__ __forceinline__ void cp_wait() {
    asm volatile("cp.async.wait_group %0;" :: "n"(N));
}
__device__ __forceinline__ void ldsm4(uint32_t* r, uint32_t a) {
    asm volatile("ldmatrix.sync.aligned.m8n8.x4.shared.b16 {%0,%1,%2,%3}, [%4];"
        : "=r"(r[0]), "=r"(r[1]), "=r"(r[2]), "=r"(r[3]) : "r"(a));
}
__device__ __forceinline__ void ldsm4t(uint32_t* r, uint32_t a) {
    asm volatile("ldmatrix.sync.aligned.m8n8.x4.trans.shared.b16 {%0,%1,%2,%3}, [%4];"
        : "=r"(r[0]), "=r"(r[1]), "=r"(r[2]), "=r"(r[3]) : "r"(a));
}
__device__ __forceinline__ void mma_bf16(float* c, const uint32_t* a,
                                         const uint32_t* b) {
    asm volatile(
        "mma.sync.aligned.m16n8k16.row.col.f32.bf16.bf16.f32 "
        "{%0,%1,%2,%3}, {%4,%5,%6,%7}, {%8,%9}, {%0,%1,%2,%3};"
        : "+f"(c[0]), "+f"(c[1]), "+f"(c[2]), "+f"(c[3])
        : "r"(a[0]), "r"(a[1]), "r"(a[2]), "r"(a[3]), "r"(b[0]), "r"(b[1]));
}
__device__ __forceinline__ uint32_t packbf(float e0, float e1) {
    uint32_t r;
    asm("cvt.rn.bf16x2.f32 %0, %1, %2;" : "=r"(r) : "f"(e1), "f"(e0));
    return r;
}
__device__ __forceinline__ uint32_t lopackbf(uint32_t hipack, float e0, float e1) {
    float h0 = __uint_as_float(hipack << 16);
    float h1 = __uint_as_float(hipack & 0xffff0000u);
    return packbf(e0 - h0, e1 - h1);
}
__device__ __forceinline__ float ex2f(float x) {
    float y;
    asm("ex2.approx.ftz.f32 %0, %1;" : "=f"(y) : "f"(x));
    return y;
}
// 64B-row swizzle: bits [4:5] ^= bits [7:8]. Apply to the FULL sub-bit-10
// logical offset; only multiples of 1024 may be added post-swizzle.
__device__ __forceinline__ uint32_t swz(uint32_t off) {
    return off ^ (((off >> 7) & 3u) << 4);
}

// ---------------------------------------------------------------------------
// Split fp32 -> (hi, lo) bf16 (elementwise)
// ---------------------------------------------------------------------------
__global__ __launch_bounds__(256)
void split_kernel(const float* __restrict__ in, __nv_bfloat16* __restrict__ hi,
                  __nv_bfloat16* __restrict__ lo, int n)
{
    int i = (blockIdx.x * 256 + threadIdx.x) * 4;
    if (i >= n) return;
    float4 v = *(const float4*)(in + i);
    uint32_t h0 = packbf(v.x, v.y);
    uint32_t h1 = packbf(v.z, v.w);
    *(uint32_t*)(hi + i)     = h0;
    *(uint32_t*)(hi + i + 2) = h1;
    *(uint32_t*)(lo + i)     = lopackbf(h0, v.x, v.y);
    *(uint32_t*)(lo + i + 2) = lopackbf(h1, v.z, v.w);
}

// ---------------------------------------------------------------------------
// Transpose + split: W fp32 [K][N] -> Whi/Wlo bf16 [N][K]
// ---------------------------------------------------------------------------
__global__ __launch_bounds__(256)
void tsplit_kernel(const float* __restrict__ W, __nv_bfloat16* __restrict__ hi,
                   __nv_bfloat16* __restrict__ lo, int K, int N)
{
    __shared__ float t[32][33];
    const int n0 = blockIdx.x * 32, k0 = blockIdx.y * 32;
    const int x = threadIdx.x & 31, y = threadIdx.x >> 5;
#pragma unroll
    for (int i = 0; i < 4; i++)
        t[y + 8 * i][x] = W[(size_t)(k0 + y + 8 * i) * N + n0 + x];
    __syncthreads();
#pragma unroll
    for (int i = 0; i < 4; i++) {
        float v = t[x][y + 8 * i];
        __nv_bfloat16 h = __float2bfloat16(v);
        size_t o = (size_t)(n0 + y + 8 * i) * K + k0 + x;
        hi[o] = h;
        lo[o] = __float2bfloat16(v - __bfloat162float(h));
    }
}

// ---------------------------------------------------------------------------
// HMMA bf16x3 GEMM: C = A @ B^T  (B stored [N][K] K-major)
// 128x128 tile, BK=32, 8 warps, 3-stage cp.async pipeline, swizzled smem.
// ONE barrier per chunk: the top barrier of chunk kc proves all warps are
// done with kc-1, whose stage ((kc-1)%3 == (kc+2)%3) is the prefetch target.
// ---------------------------------------------------------------------------
#define BKC        32
#define OPB        (128 * 64)               // 8192 B per operand tile
#define STGB       (4 * OPB)                // 32768 B per stage
#define NSTG       3
#define GEMM_SMEM  (NSTG * STGB)            // 98304 B

__device__ __forceinline__ void load_op(uint32_t dstb,
                                        const __nv_bfloat16* __restrict__ src,
                                        int r0, int k0, int K, int tid)
{
#pragma unroll
    for (int t = 0; t < 2; t++) {
        const int i = tid + t * 256;        // 0..511
        const int row = i >> 2, seg = i & 3;
        cpa16(dstb + swz((uint32_t)(row * 64 + seg * 16)),
              src + (size_t)(r0 + row) * K + k0 + seg * 8);
    }
}

__device__ __forceinline__ void load_stage(
    uint32_t sbase,
    const __nv_bfloat16* __restrict__ Ahi, const __nv_bfloat16* __restrict__ Alo,
    const __nv_bfloat16* __restrict__ Bhi, const __nv_bfloat16* __restrict__ Blo,
    int m0, int n0, int k0, int K, int tid)
{
    load_op(sbase + 0 * OPB, Ahi, m0, k0, K, tid);
    load_op(sbase + 1 * OPB, Alo, m0, k0, K, tid);
    load_op(sbase + 2 * OPB, Bhi, n0, k0, K, tid);
    load_op(sbase + 3 * OPB, Blo, n0, k0, K, tid);
}

__global__ __launch_bounds__(256, 2)
void gemm_hmma(const __nv_bfloat16* __restrict__ Ahi,
               const __nv_bfloat16* __restrict__ Alo,
               const __nv_bfloat16* __restrict__ Bhi,
               const __nv_bfloat16* __restrict__ Blo,
               float* __restrict__ Cf,
               __nv_bfloat16* __restrict__ Chi,
               __nv_bfloat16* __restrict__ Clo,
               int M, int N, int K)
{
    extern __shared__ char smc[];
    const uint32_t sb = smem_u32(smc);
    const int tid  = threadIdx.x;
    const int wid  = tid >> 5, lane = tid & 31;
    const int wm   = wid >> 2;
    const int wn   = wid & 3;
    const int g    = lane >> 2;
    const int tig  = lane & 3;
    const int m0 = blockIdx.y * 128, n0 = blockIdx.x * 128;

    const int lrow  = lane & 15;
    const int lhalf = lane >> 4;
    const int brow  = (lane & 7) | ((lane & 16) >> 1);
    const int bhalf = (lane >> 3) & 1;

    // per-ks swizzled fragment bases (k-step folded in pre-swizzle)
    uint32_t aoff[2], boff[2];
#pragma unroll
    for (int ks = 0; ks < 2; ks++) {
        aoff[ks] = swz((uint32_t)((wm * 64 + lrow) * 64 + lhalf * 16 + ks * 32));
        boff[ks] = swz((uint32_t)((wn * 32 + brow) * 64 + bhalf * 16 + ks * 32));
    }

    float acc[4][4][4];
#pragma unroll
    for (int mt = 0; mt < 4; mt++)
#pragma unroll
        for (int nt = 0; nt < 4; nt++)
#pragma unroll
            for (int q = 0; q < 4; q++) acc[mt][nt][q] = 0.0f;

    const int NC = K / BKC;

    load_stage(sb, Ahi, Alo, Bhi, Blo, m0, n0, 0, K, tid);
    cp_commit();
    load_stage(sb + STGB, Ahi, Alo, Bhi, Blo, m0, n0, BKC, K, tid);
    cp_commit();

    int st_idx = 0;
    for (int kc = 0; kc < NC; kc++) {
        if (kc + 1 < NC) cp_wait<1>(); else cp_wait<0>();
        __syncthreads();   // chunk kc visible; all warps done with kc-1

        // early prefetch: chunk kc+2 into stage (kc+2)%3 (== (kc-1)%3)
        if (kc + 2 < NC) {
            int nst = st_idx + 2; if (nst >= NSTG) nst -= NSTG;
            load_stage(sb + (uint32_t)nst * STGB,
                       Ahi, Alo, Bhi, Blo, m0, n0, (kc + 2) * BKC, K, tid);
            cp_commit();
        }

        const uint32_t st = sb + (uint32_t)st_idx * STGB;
#pragma unroll
        for (int ks = 0; ks < 2; ks++) {
            const uint32_t aB = st + aoff[ks];
            const uint32_t bB = st + 2u * OPB + boff[ks];

            uint32_t bh[2][4], bl[2][4];
#pragma unroll
            for (int pr = 0; pr < 2; pr++) {
                ldsm4(bh[pr], bB + (uint32_t)(pr * 1024));
                ldsm4(bl[pr], bB + OPB + (uint32_t)(pr * 1024));
            }
#pragma unroll
            for (int mt = 0; mt < 4; mt++) {
                uint32_t ah[4], al[4];
                ldsm4(ah, aB + (uint32_t)(mt * 1024));
                ldsm4(al, aB + OPB + (uint32_t)(mt * 1024));
#pragma unroll
                for (int nt = 0; nt < 4; nt++) {
                    const uint32_t* bhp = &bh[nt >> 1][(nt & 1) * 2];
                    const uint32_t* blp = &bl[nt >> 1][(nt & 1) * 2];
                    mma_bf16(acc[mt][nt], ah, bhp);
                    mma_bf16(acc[mt][nt], ah, blp);
                    mma_bf16(acc[mt][nt], al, bhp);
                }
            }
        }
        // no tail barrier: next chunk's top barrier provides the edge
        if (++st_idx == NSTG) st_idx = 0;
    }

#pragma unroll
    for (int mt = 0; mt < 4; mt++) {
        const int row = m0 + wm * 64 + mt * 16 + g;
#pragma unroll
        for (int nt = 0; nt < 4; nt++) {
            const int col = n0 + wn * 32 + nt * 8 + tig * 2;
            if (Cf) {
                *(float2*)&Cf[(size_t)row * N + col] =
                    make_float2(acc[mt][nt][0], acc[mt][nt][1]);
                *(float2*)&Cf[(size_t)(row + 8) * N + col] =
                    make_float2(acc[mt][nt][2], acc[mt][nt][3]);
            } else {
                uint32_t h0 = packbf(acc[mt][nt][0], acc[mt][nt][1]);
                uint32_t h1 = packbf(acc[mt][nt][2], acc[mt][nt][3]);
                *(uint32_t*)&Chi[(size_t)row * N + col]       = h0;
                *(uint32_t*)&Chi[(size_t)(row + 8) * N + col] = h1;
                *(uint32_t*)&Clo[(size_t)row * N + col] =
                    lopackbf(h0, acc[mt][nt][0], acc[mt][nt][1]);
                *(uint32_t*)&Clo[(size_t)(row + 8) * N + col] =
                    lopackbf(h1, acc[mt][nt][2], acc[mt][nt][3]);
            }
        }
    }
}

// ---------------------------------------------------------------------------
// HMMA flash attention (causal). K and V prefetch are SEPARATE commit groups:
// K(kt+1) loads overlap the P·V phase of kt; V(kt+1) loads overlap the
// S-phase of kt+1. Groups complete in order, so each cp_wait<1> retires
// exactly the group needed next; every wait is followed by a barrier for
// cross-thread smem visibility.
// ---------------------------------------------------------------------------
#define SKVB   272
#define TILEB  (64 * SKVB)
#define ATTN_SMEM (6 * TILEB)
#define CL2E   (0.08838834764831845f * 1.4426950408889634f)

__global__ __launch_bounds__(128)
void attn_mma(const __nv_bfloat16* __restrict__ qh,
              const __nv_bfloat16* __restrict__ ql,
              __nv_bfloat16* __restrict__ ohi,
              __nv_bfloat16* __restrict__ olo)
{
    extern __shared__ char sma[];
    const uint32_t sb = smem_u32(sma);
    const int qt = (int)gridDim.x - 1 - (int)blockIdx.x;
    const int h = blockIdx.y, b = blockIdx.z;
    const int tid = threadIdx.x, lane = tid & 31, w = tid >> 5;
    const int g = lane >> 2, tig = lane & 3;
    const int lrow = lane & 15, lhalf = lane >> 4;
    const int brow = (lane & 7) | ((lane & 16) >> 1), bhalf = (lane >> 3) & 1;

    const uint32_t sQH = sb, sQL = sb + TILEB;
    const uint32_t sKH = sb + 2 * TILEB, sKL = sb + 3 * TILEB;
    const uint32_t sVH = sb + 4 * TILEB, sVL = sb + 5 * TILEB;

    const size_t qrow0 = (size_t)b * TSEQ + (size_t)qt * 64;

    // initial loads: Q + K0 + V0, one group
    {
        const __nv_bfloat16* qbh = qh + qrow0 * NQKV + h * HD;
        const __nv_bfloat16* qbl = ql + qrow0 * NQKV + h * HD;
        const size_t kr0 = (size_t)b * TSEQ;
        const __nv_bfloat16* kh = qh + kr0 * NQKV + D_MODEL + h * HD;
        const __nv_bfloat16* kl = ql + kr0 * NQKV + D_MODEL + h * HD;
        const __nv_bfloat16* vh = qh + kr0 * NQKV + 2 * D_MODEL + h * HD;
        const __nv_bfloat16* vl = ql + kr0 * NQKV + 2 * D_MODEL + h * HD;
#pragma unroll
        for (int it = 0; it < 8; it++) {
            int idx = tid + it * 128;
            int r = idx >> 4, cs = idx & 15;
            uint32_t so = (uint32_t)(r * SKVB + cs * 16);
            size_t go = (size_t)r * NQKV + cs * 8;
            cpa16(sQH + so, qbh + go); cpa16(sQL + so, qbl + go);
            cpa16(sKH + so, kh + go);  cpa16(sKL + so, kl + go);
            cpa16(sVH + so, vh + go);  cpa16(sVL + so, vl + go);
        }
    }
    cp_commit();
    cp_wait<0>();
    __syncthreads();

    float o[16][4];
#pragma unroll
    for (int t = 0; t < 16; t++)
#pragma unroll
        for (int q = 0; q < 4; q++) o[t][q] = 0.0f;
    float mi0 = -1e30f, mi1 = -1e30f, li0 = 0.0f, li1 = 0.0f;

    const uint32_t aH = sQH + (uint32_t)((w * 16 + lrow) * SKVB + lhalf * 16);
    const uint32_t aL = sQL + (uint32_t)((w * 16 + lrow) * SKVB + lhalf * 16);
    const uint32_t bH = sKH + (uint32_t)(brow * SKVB + bhalf * 16);
    const uint32_t bL = sKL + (uint32_t)(brow * SKVB + bhalf * 16);
    const uint32_t vH = sVH + (uint32_t)((lane & 15) * SKVB + (lane >> 4) * 16);
    const uint32_t vL = sVL + (uint32_t)((lane & 15) * SKVB + (lane >> 4) * 16);

    for (int kt = 0; kt <= qt; kt++) {
        // ---- S = Q K^T (bf16x3) ----
        float sc[8][4];
#pragma unroll
        for (int nt = 0; nt < 8; nt++)
#pragma unroll
            for (int q = 0; q < 4; q++) sc[nt][q] = 0.0f;

#pragma unroll
        for (int s = 0; s < 8; s++) {
            const uint32_t kb = (uint32_t)(s * 32);
            uint32_t ah[4], al[4];
            ldsm4(ah, aH + kb);
            ldsm4(al, aL + kb);
            uint32_t kh4[4][4], kl4[4][4];
#pragma unroll
            for (int p = 0; p < 4; p++) {
                ldsm4(kh4[p], bH + (uint32_t)(p * 16 * SKVB) + kb);
                ldsm4(kl4[p], bL + (uint32_t)(p * 16 * SKVB) + kb);
            }
#pragma unroll
            for (int nt = 0; nt < 8; nt++) {
                const uint32_t* bhp = &kh4[nt >> 1][(nt & 1) * 2];
                const uint32_t* blp = &kl4[nt >> 1][(nt & 1) * 2];
                mma_bf16(sc[nt], ah, bhp);
                mma_bf16(sc[nt], ah, blp);
                mma_bf16(sc[nt], al, bhp);
            }
        }

        // ---- causal mask (diagonal tile only) ----
        if (kt == qt) {
            const int r0 = w * 16 + g, r1 = r0 + 8;
#pragma unroll
            for (int nt = 0; nt < 8; nt++) {
                const int c0 = nt * 8 + 2 * tig;
                if (c0     > r0) sc[nt][0] = -1e30f;
                if (c0 + 1 > r0) sc[nt][1] = -1e30f;
                if (c0     > r1) sc[nt][2] = -1e30f;
                if (c0 + 1 > r1) sc[nt][3] = -1e30f;
            }
        }

        // ---- online softmax ----
        float m0 = -1e30f, m1 = -1e30f;
#pragma unroll
        for (int nt = 0; nt < 8; nt++) {
            m0 = fmaxf(m0, fmaxf(sc[nt][0], sc[nt][1]));
            m1 = fmaxf(m1, fmaxf(sc[nt][2], sc[nt][3]));
        }
        m0 = fmaxf(m0, __shfl_xor_sync(0xffffffffu, m0, 1));
        m0 = fmaxf(m0, __shfl_xor_sync(0xffffffffu, m0, 2));
        m1 = fmaxf(m1, __shfl_xor_sync(0xffffffffu, m1, 1));
        m1 = fmaxf(m1, __shfl_xor_sync(0xffffffffu, m1, 2));
        const float n0 = fmaxf(mi0, m0), n1 = fmaxf(mi1, m1);
        const float c0 = ex2f((mi0 - n0) * CL2E);
        const float c1 = ex2f((mi1 - n1) * CL2E);
        mi0 = n0; mi1 = n1;
        float r0 = 0.0f, r1 = 0.0f;
#pragma unroll
        for (int nt = 0; nt < 8; nt++) {
            sc[nt][0] = ex2f((sc[nt][0] - n0) * CL2E);
            sc[nt][1] = ex2f((sc[nt][1] - n0) * CL2E);
            sc[nt][2] = ex2f((sc[nt][2] - n1) * CL2E);
            sc[nt][3] = ex2f((sc[nt][3] - n1) * CL2E);
            r0 += sc[nt][0] + sc[nt][1];
            r1 += sc[nt][2] + sc[nt][3];
        }
        r0 += __shfl_xor_sync(0xffffffffu, r0, 1);
        r0 += __shfl_xor_sync(0xffffffffu, r0, 2);
        r1 += __shfl_xor_sync(0xffffffffu, r1, 1);
        r1 += __shfl_xor_sync(0xffffffffu, r1, 2);
        li0 = li0 * c0 + r0;
        li1 = li1 * c1 + r1;
#pragma unroll
        for (int t = 0; t < 16; t++) {
            o[t][0] *= c0; o[t][1] *= c0;
            o[t][2] *= c1; o[t][3] *= c1;
        }

        // ---- prefetch K(kt+1): overlaps the P·V phase below ----
        if (kt < qt) {
            __syncthreads();                       // all warps done reading Kcur
            const size_t kr0 = (size_t)b * TSEQ + (size_t)(kt + 1) * 64;
            const __nv_bfloat16* kh = qh + kr0 * NQKV + D_MODEL + h * HD;
            const __nv_bfloat16* kl = ql + kr0 * NQKV + D_MODEL + h * HD;
#pragma unroll
            for (int it = 0; it < 8; it++) {
                int idx = tid + it * 128;
                int r = idx >> 4, cs = idx & 15;
                uint32_t so = (uint32_t)(r * SKVB + cs * 16);
                size_t go = (size_t)r * NQKV + cs * 8;
                cpa16(sKH + so, kh + go); cpa16(sKL + so, kl + go);
            }
            cp_commit();
            cp_wait<1>();                          // Vcur group complete
            __syncthreads();                       // Vcur visible to all warps
        }

        // ---- O += P V (bf16x3) ----
#pragma unroll
        for (int s = 0; s < 4; s++) {
            uint32_t phi[4], plo[4];
            phi[0] = packbf(sc[2*s][0],   sc[2*s][1]);
            phi[1] = packbf(sc[2*s][2],   sc[2*s][3]);
            phi[2] = packbf(sc[2*s+1][0], sc[2*s+1][1]);
            phi[3] = packbf(sc[2*s+1][2], sc[2*s+1][3]);
            plo[0] = lopackbf(phi[0], sc[2*s][0],   sc[2*s][1]);
            plo[1] = lopackbf(phi[1], sc[2*s][2],   sc[2*s][3]);
            plo[2] = lopackbf(phi[2], sc[2*s+1][0], sc[2*s+1][1]);
            plo[3] = lopackbf(phi[3], sc[2*s+1][2], sc[2*s+1][3]);

            const uint32_t vrow = (uint32_t)(s * 16 * SKVB);
#pragma unroll
            for (int p = 0; p < 8; p++) {
                uint32_t vh4[4], vl4[4];
                ldsm4t(vh4, vH + vrow + (uint32_t)(p * 32));
                ldsm4t(vl4, vL + vrow + (uint32_t)(p * 32));
                mma_bf16(o[2*p],   phi, &vh4[0]);
                mma_bf16(o[2*p],   plo, &vh4[0]);
                mma_bf16(o[2*p],   phi, &vl4[0]);
                mma_bf16(o[2*p+1], phi, &vh4[2]);
                mma_bf16(o[2*p+1], plo, &vh4[2]);
                mma_bf16(o[2*p+1], phi, &vl4[2]);
            }
        }

        // ---- prefetch V(kt+1): overlaps the next S-phase ----
        if (kt < qt) {
            __syncthreads();                       // all warps done reading Vcur
            const size_t kr0 = (size_t)b * TSEQ + (size_t)(kt + 1) * 64;
            const __nv_bfloat16* vh = qh + kr0 * NQKV + 2 * D_MODEL + h * HD;
            const __nv_bfloat16* vl = ql + kr0 * NQKV + 2 * D_MODEL + h * HD;
#pragma unroll
            for (int it = 0; it < 8; it++) {
                int idx = tid + it * 128;
                int r = idx >> 4, cs = idx & 15;
                uint32_t so = (uint32_t)(r * SKVB + cs * 16);
                size_t go = (size_t)r * NQKV + cs * 8;
                cpa16(sVH + so, vh + go); cpa16(sVL + so, vl + go);
            }
            cp_commit();
            cp_wait<1>();                          // K(kt+1) group complete
            __syncthreads();                       // K(kt+1) visible
        }
    }

    // ---- epilogue: normalize, split bf16 hi/lo ----
    const float inv0 = 1.0f / li0, inv1 = 1.0f / li1;
    const size_t row0 = qrow0 + w * 16 + g, row1 = row0 + 8;
#pragma unroll
    for (int nt = 0; nt < 16; nt++) {
        const int col = h * HD + nt * 8 + 2 * tig;
        float a0 = o[nt][0] * inv0, a1 = o[nt][1] * inv0;
        float a2 = o[nt][2] * inv1, a3 = o[nt][3] * inv1;
        uint32_t h0 = packbf(a0, a1), h1 = packbf(a2, a3);
        *(uint32_t*)&ohi[row0 * D_MODEL + col] = h0;
        *(uint32_t*)&ohi[row1 * D_MODEL + col] = h1;
        *(uint32_t*)&olo[row0 * D_MODEL + col] = lopackbf(h0, a0, a1);
        *(uint32_t*)&olo[row1 * D_MODEL + col] = lopackbf(h1, a2, a3);
    }
}

// ---------------------------------------------------------------------------
extern "C" void kernel_launch(void* const* d_in, const int* in_sizes, int n_in,
                              void* d_out, int out_size)
{
    (void)in_sizes; (void)n_in; (void)out_size;
    const float* x      = (const float*)d_in[0];
    const float* w_qkv  = (const float*)d_in[1];
    const float* w_proj = (const float*)d_in[2];
    float* out = (float*)d_out;

    __nv_bfloat16 *qhi, *qlo, *xhi, *xlo, *ahi, *alo, *wqhi, *wqlo, *wphi, *wplo;
    cudaGetSymbolAddress((void**)&qhi,  g_qkvhi);
    cudaGetSymbolAddress((void**)&qlo,  g_qkvlo);
    cudaGetSymbolAddress((void**)&xhi,  g_xhi);
    cudaGetSymbolAddress((void**)&xlo,  g_xlo);
    cudaGetSymbolAddress((void**)&ahi,  g_ahi);
    cudaGetSymbolAddress((void**)&alo,  g_alo);
    cudaGetSymbolAddress((void**)&wqhi, g_wqhi);
    cudaGetSymbolAddress((void**)&wqlo, g_wqlo);
    cudaGetSymbolAddress((void**)&wphi, g_wphi);
    cudaGetSymbolAddress((void**)&wplo, g_wplo);

    cudaFuncSetAttribute(gemm_hmma,
                         cudaFuncAttributeMaxDynamicSharedMemorySize, GEMM_SMEM);
    cudaFuncSetAttribute(attn_mma,
                         cudaFuncAttributeMaxDynamicSharedMemorySize, ATTN_SMEM);

    const int nx = MTOT * D_MODEL;

    split_kernel<<<nx / 4 / 256, 256>>>(x, xhi, xlo, nx);
    tsplit_kernel<<<dim3(NQKV / 32, D_MODEL / 32), 256>>>(w_qkv, wqhi, wqlo,
                                                          D_MODEL, NQKV);
    tsplit_kernel<<<dim3(D_MODEL / 32, D_MODEL / 32), 256>>>(w_proj, wphi, wplo,
                                                             D_MODEL, D_MODEL);
    gemm_hmma<<<dim3(NQKV / 128, MTOT / 128), 256, GEMM_SMEM>>>(
        xhi, xlo, wqhi, wqlo, nullptr, qhi, qlo, MTOT, NQKV, D_MODEL);
    attn_mma<<<dim3(TSEQ / 64, NHEAD, BATCH), 128, ATTN_SMEM>>>(
        qhi, qlo, ahi, alo);
    gemm_hmma<<<dim3(D_MODEL / 128, MTOT / 128), 256, GEMM_SMEM>>>(
        ahi, alo, wphi, wplo, out, nullptr, nullptr, MTOT, D_MODEL, D_MODEL);
}